// round 12
// baseline (speedup 1.0000x reference)
#include <cuda_runtime.h>
#include <cstdint>
#include <math.h>

#define CB 4
#define CS 1024
#define CH 1024
#define CNH 16
#define CDH 64
#define CM (CB*CS)
#define CLIPV 2.5f

typedef unsigned long long u64t;
#define FMA_F32X2(d,a,b,c) asm("fma.rn.f32x2 %0,%1,%2,%3;" : "=l"(d) : "l"(a),"l"(b),"l"(c))
#define ADD_F32X2_(d,a,b)  asm("add.rn.f32x2 %0,%1,%2;"    : "=l"(d) : "l"(a),"l"(b))

// ---------------- scratch (device globals; no allocations allowed) ----------
__device__ unsigned g_max[8];   // 0 hidden,1 Wq,2 Wk,3 Wv,4 q,5 k,6 v,7 probs
__device__ float  g_xd[(size_t)CM*CH];                // dequant hidden (bit-exact)
__device__ float  g_wd[3][(size_t)CH*CH];             // dequant weights (bit-exact)
__device__ float  g_lin[3][(size_t)CM*CH];            // q,k,v fp32 [B,S,H]
__device__ float  g_qf[(size_t)CB*CNH*CS*CDH];        // dequant q [b,h,s,d] fp32
__device__ float  g_kf[(size_t)CB*CNH*CS*CDH];        // dequant k [b,h,s,d] fp32
__device__ int8_t g_v8t[(size_t)CB*CNH*CDH*CS];       // v codes [b,h,d,s]
__device__ float  g_sc_fb[(size_t)CB*CNH*CS*CS];      // fallback scores
__device__ float  g_pr_fb[(size_t)CB*CNH*CS*CS];      // fallback probs

__device__ __forceinline__ float clipf(float v){ return fminf(fmaxf(v,-CLIPV),CLIPV); }
__device__ __forceinline__ float slot_m(int s){ return fmaxf(__uint_as_float(g_max[s]),1e-8f); }
__device__ __forceinline__ float lo32(u64t v){ return __uint_as_float((unsigned)(v & 0xffffffffu)); }
__device__ __forceinline__ float hi32(u64t v){ return __uint_as_float((unsigned)(v >> 32)); }

// Eigen pexp<float> replica (unchanged from passing R11 kernel).
__device__ __forceinline__ float exp_eig(float x){
  float m = floorf(__fmaf_rn(x, 1.44269504088896341f, 0.5f));
  float r = __fmaf_rn(m, -0.693359375f, x);
  r = __fmaf_rn(m, 2.12194440e-4f, r);
  float r2 = __fmul_rn(r, r);
  float r3 = __fmul_rn(r2, r);
  float y, y1, y2;
  y  = __fmaf_rn(1.9875691500e-4f, r, 1.3981999507e-3f);
  y1 = __fmaf_rn(4.1665795894e-2f, r, 1.6666665459e-1f);
  y2 = __fadd_rn(r, 1.0f);
  y  = __fmaf_rn(y, r, 8.3334519073e-3f);
  y1 = __fmaf_rn(y1, r, 5.0000001201e-1f);
  y  = __fmaf_rn(y, r3, y1);
  y  = __fmaf_rn(y, r2, y2);
  int mi = (int)m;
  return __fmul_rn(y, __int_as_float((mi + 127) << 23));
}

__global__ void k_init(){ if(threadIdx.x<8) g_max[threadIdx.x]=0u; }

__global__ void k_absmax(const float* __restrict__ x, int n4, int slot){
  float m=0.f;
  for (int i=blockIdx.x*blockDim.x+threadIdx.x; i<n4; i+=gridDim.x*blockDim.x){
    float4 v=((const float4*)x)[i];
    m=fmaxf(m,fabsf(clipf(v.x))); m=fmaxf(m,fabsf(clipf(v.y)));
    m=fmaxf(m,fabsf(clipf(v.z))); m=fmaxf(m,fabsf(clipf(v.w)));
  }
  #pragma unroll
  for(int o=16;o;o>>=1) m=fmaxf(m,__shfl_xor_sync(0xffffffffu,m,o));
  if((threadIdx.x&31)==0) atomicMax(&g_max[slot],__float_as_uint(m));
}

__global__ void k_quant(const float* __restrict__ x, int n, int slot, int wid){
  float* o = (wid<0)? g_xd : g_wd[wid];
  float s = __fdiv_rn(127.f, slot_m(slot));
  for(int i=blockIdx.x*blockDim.x+threadIdx.x;i<n;i+=gridDim.x*blockDim.x){
    float q = rintf(__fmul_rn(clipf(x[i]), s));
    o[i] = __fdiv_rn(q, s);
  }
}

// ---- fp32 projection GEMM, Eigen panels [512,512], packed f32x2 FMA --------
// Per output element the arithmetic is IDENTICAL to the passing scalar
// version: ascending-k fp32 RN FMA chain per panel, panels combined by one
// RN add, bias last. f32x2 packs two OUTPUT COLUMNS per instruction; each
// lane is a full IEEE fp32 lane. BM=128, BN=64, BK=16, 256 thr, 8x4 outputs.
__global__ __launch_bounds__(256,2) void k_gemm(const float* __restrict__ bq,
                                                const float* __restrict__ bk,
                                                const float* __restrict__ bv){
  __shared__ float As2[16][256];   // A duplicated: [kk][2*row] = [kk][2*row+1]
  __shared__ float Bs [16][64];    // [kk][n]
  int which = blockIdx.z;
  const float* bias = (which==0)? bq : (which==1)? bk : bv;
  const float* A = g_xd;
  const float* W = g_wd[which];
  float* C = g_lin[which];
  int bm=blockIdx.x, bn=blockIdx.y;
  int tid=threadIdx.x, ty=tid>>4, tx=tid&15;
  const float* Ab = A + (size_t)bm*128*CH;
  const float* Wb = W + (size_t)bn*64*CH;
  int arow0 = tid>>1;          // 0..127 (A row for first float4)
  int ak4   = (tid&1)*2;       // 0 or 2 (which pair of float4s in k)
  int brow  = tid>>2;          // 0..63
  int bk4   = tid&3;           // 0..3
  u64t acc[8][2]={}, tot[8][2]={};
  // prefetch tile 0
  float4 ra0 = *(const float4*)(Ab + (size_t)arow0*CH + ak4*4);
  float4 ra1 = *(const float4*)(Ab + (size_t)arow0*CH + (ak4+1)*4);
  float4 rb  = *(const float4*)(Wb + (size_t)brow *CH + bk4*4);
  for(int kt=0;kt<64;kt++){
    __syncthreads();
    {
      float2* a0=(float2*)As2[ak4*4+0]; float2* a1=(float2*)As2[ak4*4+1];
      float2* a2p=(float2*)As2[ak4*4+2]; float2* a3=(float2*)As2[ak4*4+3];
      a0[arow0]=make_float2(ra0.x,ra0.x); a1[arow0]=make_float2(ra0.y,ra0.y);
      a2p[arow0]=make_float2(ra0.z,ra0.z); a3[arow0]=make_float2(ra0.w,ra0.w);
      float2* a4=(float2*)As2[(ak4+1)*4+0]; float2* a5=(float2*)As2[(ak4+1)*4+1];
      float2* a6=(float2*)As2[(ak4+1)*4+2]; float2* a7=(float2*)As2[(ak4+1)*4+3];
      a4[arow0]=make_float2(ra1.x,ra1.x); a5[arow0]=make_float2(ra1.y,ra1.y);
      a6[arow0]=make_float2(ra1.z,ra1.z); a7[arow0]=make_float2(ra1.w,ra1.w);
      Bs[bk4*4+0][brow]=rb.x; Bs[bk4*4+1][brow]=rb.y;
      Bs[bk4*4+2][brow]=rb.z; Bs[bk4*4+3][brow]=rb.w;
    }
    __syncthreads();
    if(kt<63){
      ra0 = *(const float4*)(Ab + (size_t)arow0*CH + (kt+1)*16 + ak4*4);
      ra1 = *(const float4*)(Ab + (size_t)arow0*CH + (kt+1)*16 + (ak4+1)*4);
      rb  = *(const float4*)(Wb + (size_t)brow *CH + (kt+1)*16 + bk4*4);
    }
    if(kt==32){                 // Eigen panel boundary k=512
      #pragma unroll
      for(int i=0;i<8;i++)
        #pragma unroll
        for(int j=0;j<2;j++){ ADD_F32X2_(tot[i][j],tot[i][j],acc[i][j]); acc[i][j]=0ull; }
    }
    #pragma unroll
    for(int kk=0;kk<16;kk++){
      u64t a2[8], b2[2];
      #pragma unroll
      for(int i=0;i<8;i++) a2[i]=*(const u64t*)&As2[kk][2*(ty*8+i)];
      #pragma unroll
      for(int j=0;j<2;j++) b2[j]=*(const u64t*)&Bs[kk][2*tx+32*j];
      #pragma unroll
      for(int i=0;i<8;i++)
        #pragma unroll
        for(int j=0;j<2;j++) FMA_F32X2(acc[i][j],a2[i],b2[j],acc[i][j]);
    }
  }
  float lm=0.f;
  #pragma unroll
  for(int i=0;i<8;i++){
    int m=bm*128+ty*8+i;
    #pragma unroll
    for(int j=0;j<2;j++){
      u64t s; ADD_F32X2_(s,tot[i][j],acc[i][j]);
      int n0=bn*64+2*tx+32*j;
      float c0=__fadd_rn(lo32(s), bias[n0]);
      float c1=__fadd_rn(hi32(s), bias[n0+1]);
      *(float2*)&C[(size_t)m*CH+n0]=make_float2(c0,c1);
      lm=fmaxf(lm,fabsf(clipf(c0))); lm=fmaxf(lm,fabsf(clipf(c1)));
    }
  }
  #pragma unroll
  for(int o=16;o;o>>=1) lm=fmaxf(lm,__shfl_xor_sync(0xffffffffu,lm,o));
  if((tid&31)==0) atomicMax(&g_max[4+which],__float_as_uint(lm));
}

// ---- dequantized q/k (fp32, head-major): bit-exact sym_quant(q/k) ---------
__global__ void k_quant_headsf(int which){
  const float* src = g_lin[which];
  float* dst = (which==0)? g_qf : g_kf;
  float s = __fdiv_rn(127.f, slot_m(4+which));
  const int n = CB*CNH*CS*CDH;
  for(int i=blockIdx.x*blockDim.x+threadIdx.x;i<n;i+=gridDim.x*blockDim.x){
    int d=i&63, s_=(i>>6)&1023, h=(i>>16)&15, b=i>>20;
    float v=src[((size_t)(b*CS+s_))*CH + h*CDH + d];
    float q=rintf(__fmul_rn(clipf(v),s));
    dst[i]=__fdiv_rn(q, s);
  }
}

// ---- v: write v_q output (bit-exact) + transposed int8 codes ---------------
__global__ void k_quant_v(float* __restrict__ vq_out){
  const float* src=g_lin[2];
  float s = __fdiv_rn(127.f, slot_m(6));
  const int n = CB*CNH*CS*CDH;
  for(int i=blockIdx.x*blockDim.x+threadIdx.x;i<n;i+=gridDim.x*blockDim.x){
    int d=i&63, s_=(i>>6)&1023, h=(i>>16)&15, b=i>>20;
    float v=src[((size_t)(b*CS+s_))*CH + h*CDH + d];
    float vc=clipf(v);
    float q=rintf(__fmul_rn(vc,s));
    if(vq_out) vq_out[i]=__fdiv_rn(q, s);
    g_v8t[(((size_t)(b*CNH+h))*CDH+d)*CS + s_]=(int8_t)(int)q;
  }
}

// ---- scores: ascending-d fp32 chain (bit-exact), packed f32x2 --------------
// BM=128 q-rows, BN=64 k-cols, BK=16 (4 tiles, no panel: single chain).
__global__ __launch_bounds__(256,2) void k_scores(const float* __restrict__ mask,
                                                  float* __restrict__ ss){
  __shared__ float As2[16][256];
  __shared__ float Bs [16][64];
  int rt=blockIdx.x, ct=blockIdx.y, bh=blockIdx.z;
  int b = bh>>4;
  int tid=threadIdx.x, ty=tid>>4, tx=tid&15;
  const float* qg = g_qf + ((size_t)bh*CS + (size_t)rt*128)*CDH;
  const float* kg = g_kf + ((size_t)bh*CS + (size_t)ct*64)*CDH;
  int arow0 = tid>>1;
  int ak4   = (tid&1)*2;
  int brow  = tid>>2;
  int bk4   = tid&3;
  u64t acc[8][2]={};
  float4 ra0 = *(const float4*)(qg + (size_t)arow0*CDH + ak4*4);
  float4 ra1 = *(const float4*)(qg + (size_t)arow0*CDH + (ak4+1)*4);
  float4 rb  = *(const float4*)(kg + (size_t)brow *CDH + bk4*4);
  for(int kt=0;kt<4;kt++){
    __syncthreads();
    {
      float2* a0=(float2*)As2[ak4*4+0]; float2* a1=(float2*)As2[ak4*4+1];
      float2* a2p=(float2*)As2[ak4*4+2]; float2* a3=(float2*)As2[ak4*4+3];
      a0[arow0]=make_float2(ra0.x,ra0.x); a1[arow0]=make_float2(ra0.y,ra0.y);
      a2p[arow0]=make_float2(ra0.z,ra0.z); a3[arow0]=make_float2(ra0.w,ra0.w);
      float2* a4=(float2*)As2[(ak4+1)*4+0]; float2* a5=(float2*)As2[(ak4+1)*4+1];
      float2* a6=(float2*)As2[(ak4+1)*4+2]; float2* a7=(float2*)As2[(ak4+1)*4+3];
      a4[arow0]=make_float2(ra1.x,ra1.x); a5[arow0]=make_float2(ra1.y,ra1.y);
      a6[arow0]=make_float2(ra1.z,ra1.z); a7[arow0]=make_float2(ra1.w,ra1.w);
      Bs[bk4*4+0][brow]=rb.x; Bs[bk4*4+1][brow]=rb.y;
      Bs[bk4*4+2][brow]=rb.z; Bs[bk4*4+3][brow]=rb.w;
    }
    __syncthreads();
    if(kt<3){
      ra0 = *(const float4*)(qg + (size_t)arow0*CDH + (kt+1)*16 + ak4*4);
      ra1 = *(const float4*)(qg + (size_t)arow0*CDH + (kt+1)*16 + (ak4+1)*4);
      rb  = *(const float4*)(kg + (size_t)brow *CDH + (kt+1)*16 + bk4*4);
    }
    #pragma unroll
    for(int kk=0;kk<16;kk++){
      u64t a2[8], b2[2];
      #pragma unroll
      for(int i=0;i<8;i++) a2[i]=*(const u64t*)&As2[kk][2*(ty*8+i)];
      #pragma unroll
      for(int j=0;j<2;j++) b2[j]=*(const u64t*)&Bs[kk][2*tx+32*j];
      #pragma unroll
      for(int i=0;i<8;i++)
        #pragma unroll
        for(int j=0;j<2;j++) FMA_F32X2(acc[i][j],a2[i],b2[j],acc[i][j]);
    }
  }
  #pragma unroll
  for(int i=0;i<8;i++){
    int row = rt*128 + ty*8 + i;
    #pragma unroll
    for(int j=0;j<2;j++){
      int n0 = ct*64 + 2*tx + 32*j;
      float s0 = __fadd_rn(__fmul_rn(lo32(acc[i][j]), 0.125f), mask[b*CS+n0]);
      float s1 = __fadd_rn(__fmul_rn(hi32(acc[i][j]), 0.125f), mask[b*CS+n0+1]);
      *(float2*)&ss[((size_t)bh*CS + row)*CS + n0] = make_float2(s0,s1);
    }
  }
}

// ---- softmax per row (UNCHANGED: sum order feeds probs bits) ----------------
__global__ __launch_bounds__(256) void k_softmax(const float* __restrict__ ssrc,
                                                 float* __restrict__ pdst){
  __shared__ float red[256];
  size_t base = (size_t)blockIdx.x * CS;
  int tid=threadIdx.x;
  float4 x = *(const float4*)(ssrc + base + tid*4);
  float m = fmaxf(fmaxf(x.x,x.y), fmaxf(x.z,x.w));
  red[tid]=m; __syncthreads();
  #pragma unroll
  for(int o=128;o;o>>=1){ if(tid<o) red[tid]=fmaxf(red[tid],red[tid+o]); __syncthreads(); }
  float rowmax = red[0]; __syncthreads();
  float e0=exp_eig(__fsub_rn(x.x,rowmax));
  float e1=exp_eig(__fsub_rn(x.y,rowmax));
  float e2=exp_eig(__fsub_rn(x.z,rowmax));
  float e3=exp_eig(__fsub_rn(x.w,rowmax));
  red[tid]=((e0+e1)+(e2+e3)); __syncthreads();
  #pragma unroll
  for(int o=128;o;o>>=1){ if(tid<o) red[tid]=red[tid]+red[tid+o]; __syncthreads(); }
  float sum = red[0];
  float4 p;
  p.x=__fdiv_rn(e0,sum); p.y=__fdiv_rn(e1,sum);
  p.z=__fdiv_rn(e2,sum); p.w=__fdiv_rn(e3,sum);
  *(float4*)(pdst + base + tid*4) = p;
  if(tid==0) atomicMax(&g_max[7],__float_as_uint(__fdiv_rn(1.f,sum)));
}

// ---- PV (UNCHANGED): context_ = probs_q @ v_q -------------------------------
__global__ __launch_bounds__(256) void k_pv(const float* __restrict__ probs_in,
     float* __restrict__ ctxp, float* __restrict__ ctx){
  __shared__ int ps[128][33];
  __shared__ int vs[64][33];
  int mt=blockIdx.x, bh=blockIdx.y;
  int b=bh>>4, h=bh&15;
  const float* pg = probs_in + (((size_t)bh)*CS + (size_t)mt*128)*CS;
  const int* vtg = (const int*)(g_v8t + (size_t)bh*CDH*CS);
  float sp = __fdiv_rn(127.f, slot_m(7));
  int tid=threadIdx.x, ty=tid>>4, tx=tid&15;
  int acc[8][4]={};
  for(int kc=0;kc<8;kc++){
    for(int idx=tid; idx<128*32; idx+=256){
      int r=idx>>5, w=idx&31;
      float4 p4=*(const float4*)(pg + (size_t)r*CS + kc*128 + w*4);
      int b0=((int)rintf(__fmul_rn(p4.x,sp)))&0xFF;
      int b1=((int)rintf(__fmul_rn(p4.y,sp)))&0xFF;
      int b2=((int)rintf(__fmul_rn(p4.z,sp)))&0xFF;
      int b3=((int)rintf(__fmul_rn(p4.w,sp)))&0xFF;
      ps[r][w]= b0|(b1<<8)|(b2<<16)|(b3<<24);
    }
    for(int idx=tid; idx<64*32; idx+=256){
      int d=idx>>5, w=idx&31;
      vs[d][w]=vtg[(size_t)d*(CS/4)+kc*32+w];
    }
    __syncthreads();
    #pragma unroll
    for(int w=0;w<32;w++){
      int a[8],bb[4];
      #pragma unroll
      for(int i=0;i<8;i++) a[i]=ps[ty*8+i][w];
      #pragma unroll
      for(int j=0;j<4;j++) bb[j]=vs[tx*4+j][w];
      #pragma unroll
      for(int i=0;i<8;i++)
        #pragma unroll
        for(int j=0;j<4;j++) acc[i][j]=__dp4a(a[i],bb[j],acc[i][j]);
    }
    __syncthreads();
  }
  double inv = 1.0/((double)__fdiv_rn(127.f,slot_m(7))*(double)__fdiv_rn(127.f,slot_m(6)));
  #pragma unroll
  for(int i=0;i<8;i++){
    int srow=mt*128+ty*8+i;
    #pragma unroll
    for(int j=0;j<4;j++){
      int d=tx*4+j;
      float c=(float)((double)acc[i][j]*inv);
      if(ctxp) ctxp[(((size_t)bh)*CS+srow)*CDH+d]=c;
      ctx[((size_t)(b*CS+srow))*CH + h*CDH + d]=c;
    }
  }
}

// ---------------- launch ----------------
extern "C" void kernel_launch(void* const* d_in, const int* in_sizes, int n_in,
                              void* d_out, int out_size){
  const float* hs  =(const float*)d_in[0];
  const float* mask=(const float*)d_in[1];
  const float* Wq  =(const float*)d_in[2];
  const float* bq  =(const float*)d_in[3];
  const float* Wk  =(const float*)d_in[4];
  const float* bk  =(const float*)d_in[5];
  const float* Wv  =(const float*)d_in[6];
  const float* bv  =(const float*)d_in[7];
  float* out=(float*)d_out;

  const size_t n_ctx=(size_t)CB*CS*CH;
  const size_t n_sc =(size_t)CB*CNH*CS*CS;
  float *ctx=out, *scores=nullptr, *probs=nullptr, *ctxp=nullptr, *vq=nullptr;
  if((size_t)out_size >= 3*n_ctx + 2*n_sc){
    scores=out+n_ctx; probs=scores+n_sc; ctxp=probs+n_sc; vq=ctxp+n_ctx;
  }
  float* sc_buf = scores;
  float* pr_buf = probs;
  if(!sc_buf){ void* p; cudaGetSymbolAddress(&p, g_sc_fb); sc_buf=(float*)p; }
  if(!pr_buf){ void* p; cudaGetSymbolAddress(&p, g_pr_fb); pr_buf=(float*)p; }

  k_init<<<1,32>>>();
  k_absmax<<<512,256>>>(hs, CM*CH/4, 0);
  k_absmax<<<256,256>>>(Wq, CH*CH/4, 1);
  k_absmax<<<256,256>>>(Wk, CH*CH/4, 2);
  k_absmax<<<256,256>>>(Wv, CH*CH/4, 3);

  k_quant<<<2048,256>>>(hs, CM*CH, 0, -1);
  k_quant<<<1024,256>>>(Wq, CH*CH, 1, 0);
  k_quant<<<1024,256>>>(Wk, CH*CH, 2, 1);
  k_quant<<<1024,256>>>(Wv, CH*CH, 3, 2);

  dim3 gg(CM/128, CH/64, 3);
  k_gemm<<<gg,256>>>(bq,bk,bv);

  k_quant_headsf<<<2048,256>>>(0);
  k_quant_headsf<<<2048,256>>>(1);
  k_quant_v<<<2048,256>>>(vq);

  k_scores<<<dim3(CS/128,CS/64,CB*CNH),256>>>(mask, sc_buf);

  k_softmax<<<CB*CNH*CS,256>>>(sc_buf, pr_buf);

  k_pv<<<dim3(CS/128,CB*CNH),256>>>(pr_buf, ctxp, ctx);
}

// round 13
// speedup vs baseline: 1.0908x; 1.0908x over previous
#include <cuda_runtime.h>
#include <cstdint>
#include <math.h>

#define CB 4
#define CS 1024
#define CH 1024
#define CNH 16
#define CDH 64
#define CM (CB*CS)
#define CLIPV 2.5f

// ---------------- scratch (device globals; no allocations allowed) ----------
__device__ unsigned g_max[8];   // 0 hidden,1 Wq,2 Wk,3 Wv,4 q,5 k,6 v,7 probs
__device__ float  g_xd[(size_t)CM*CH];                // dequant hidden (bit-exact)
__device__ float  g_wd[3][(size_t)CH*CH];             // dequant weights (bit-exact)
__device__ float  g_lin[3][(size_t)CM*CH];            // q,k,v fp32 [B,S,H]
__device__ float  g_qf[(size_t)CB*CNH*CS*CDH];        // dequant q [b,h,s,d] fp32
__device__ float  g_kf[(size_t)CB*CNH*CS*CDH];        // dequant k [b,h,s,d] fp32
__device__ int8_t g_v8t[(size_t)CB*CNH*CDH*CS];       // v codes [b,h,d,s]
__device__ float  g_sc_fb[(size_t)CB*CNH*CS*CS];      // fallback scores
__device__ float  g_pr_fb[(size_t)CB*CNH*CS*CS];      // fallback probs

__device__ __forceinline__ float clipf(float v){ return fminf(fmaxf(v,-CLIPV),CLIPV); }
__device__ __forceinline__ float slot_m(int s){ return fmaxf(__uint_as_float(g_max[s]),1e-8f); }

// Eigen pexp<float> replica (unchanged bits).
__device__ __forceinline__ float exp_eig(float x){
  float m = floorf(__fmaf_rn(x, 1.44269504088896341f, 0.5f));
  float r = __fmaf_rn(m, -0.693359375f, x);
  r = __fmaf_rn(m, 2.12194440e-4f, r);
  float r2 = __fmul_rn(r, r);
  float r3 = __fmul_rn(r2, r);
  float y, y1, y2;
  y  = __fmaf_rn(1.9875691500e-4f, r, 1.3981999507e-3f);
  y1 = __fmaf_rn(4.1665795894e-2f, r, 1.6666665459e-1f);
  y2 = __fadd_rn(r, 1.0f);
  y  = __fmaf_rn(y, r, 8.3334519073e-3f);
  y1 = __fmaf_rn(y1, r, 5.0000001201e-1f);
  y  = __fmaf_rn(y, r3, y1);
  y  = __fmaf_rn(y, r2, y2);
  int mi = (int)m;
  return __fmul_rn(y, __int_as_float((mi + 127) << 23));
}

__global__ void k_init(){ if(threadIdx.x<8) g_max[threadIdx.x]=0u; }

// ---- merged abs-max over 4 tensors: grid.y = slot (0..3) --------------------
__global__ void k_absmax_all(const float* __restrict__ hs,
                             const float* __restrict__ Wq,
                             const float* __restrict__ Wk,
                             const float* __restrict__ Wv){
  int slot = blockIdx.y;
  const float* x = (slot==0)? hs : (slot==1)? Wq : (slot==2)? Wk : Wv;
  int n4 = (slot==0)? (CM*CH/4) : (CH*CH/4);
  float m=0.f;
  for (int i=blockIdx.x*blockDim.x+threadIdx.x; i<n4; i+=gridDim.x*blockDim.x){
    float4 v=((const float4*)x)[i];
    m=fmaxf(m,fabsf(clipf(v.x))); m=fmaxf(m,fabsf(clipf(v.y)));
    m=fmaxf(m,fabsf(clipf(v.z))); m=fmaxf(m,fabsf(clipf(v.w)));
  }
  #pragma unroll
  for(int o=16;o;o>>=1) m=fmaxf(m,__shfl_xor_sync(0xffffffffu,m,o));
  if((threadIdx.x&31)==0) atomicMax(&g_max[slot],__float_as_uint(m));
}

// ---- merged dequant of 4 tensors (bit-exact sym_quant fwd value) ------------
__global__ void k_quant_all(const float* __restrict__ hs,
                            const float* __restrict__ Wq,
                            const float* __restrict__ Wk,
                            const float* __restrict__ Wv){
  int slot = blockIdx.y;
  const float* x = (slot==0)? hs : (slot==1)? Wq : (slot==2)? Wk : Wv;
  float* o = (slot==0)? g_xd : g_wd[slot-1];
  int n = (slot==0)? (CM*CH) : (CH*CH);
  float s = __fdiv_rn(127.f, slot_m(slot));
  for(int i=blockIdx.x*blockDim.x+threadIdx.x;i<n;i+=gridDim.x*blockDim.x){
    float q = rintf(__fmul_rn(clipf(x[i]), s));
    o[i] = __fdiv_rn(q, s);
  }
}

// ---- fp32 projection GEMM, Eigen panels [512,512] (R11 scalar, bit-exact) ---
__global__ __launch_bounds__(256) void k_gemm(const float* __restrict__ bq,
                                              const float* __restrict__ bk,
                                              const float* __restrict__ bv){
  __shared__ float As[8][68];
  __shared__ float Bs[8][68];
  int which = blockIdx.z;
  const float* bias = (which==0)? bq : (which==1)? bk : bv;
  const float* A = g_xd;
  const float* W = g_wd[which];
  float* C = g_lin[which];
  int bm=blockIdx.x, bn=blockIdx.y;
  int tid=threadIdx.x, ty=tid>>4, tx=tid&15;
  const float* Ab = A + (size_t)bm*64*CH;
  const float* Wb = W + (size_t)bn*64*CH;
  int row=tid>>2, kp=(tid&3)*2;
  float acc[4][4]={}, tot[4][4]={};
  for(int kt=0;kt<128;kt++){
    if(kt==64){                          // panel boundary k=512
      #pragma unroll
      for(int i=0;i<4;i++)
        #pragma unroll
        for(int j=0;j<4;j++){ tot[i][j]=__fadd_rn(tot[i][j],acc[i][j]); acc[i][j]=0.f; }
    }
    float2 va=*(const float2*)(Ab+(size_t)row*CH+kt*8+kp);
    float2 vb=*(const float2*)(Wb+(size_t)row*CH+kt*8+kp);
    __syncthreads();
    As[kp][row]=va.x; As[kp+1][row]=va.y;
    Bs[kp][row]=vb.x; Bs[kp+1][row]=vb.y;
    __syncthreads();
    #pragma unroll
    for(int kk=0;kk<8;kk++){
      float a[4],b[4];
      #pragma unroll
      for(int i=0;i<4;i++) a[i]=As[kk][ty*4+i];
      #pragma unroll
      for(int j=0;j<4;j++) b[j]=Bs[kk][tx*4+j];
      #pragma unroll
      for(int i=0;i<4;i++)
        #pragma unroll
        for(int j=0;j<4;j++) acc[i][j]=__fmaf_rn(a[i],b[j],acc[i][j]);
    }
  }
  float lm=0.f;
  #pragma unroll
  for(int i=0;i<4;i++){
    int m=bm*64+ty*4+i;
    #pragma unroll
    for(int j=0;j<4;j++){
      int n=bn*64+tx*4+j;
      float c=__fadd_rn(__fadd_rn(tot[i][j],acc[i][j]), bias[n]);
      C[(size_t)m*CH+n]=c;
      lm=fmaxf(lm,fabsf(clipf(c)));
    }
  }
  #pragma unroll
  for(int o=16;o;o>>=1) lm=fmaxf(lm,__shfl_xor_sync(0xffffffffu,lm,o));
  if((tid&31)==0) atomicMax(&g_max[4+which],__float_as_uint(lm));
}

// ---- merged q/k/v re-quantization: grid.y = which (0:q,1:k,2:v) -------------
__global__ void k_quant_heads_all(float* __restrict__ vq_out){
  int which = blockIdx.y;
  const float* src = g_lin[which];
  float s = __fdiv_rn(127.f, slot_m(4+which));
  const int n = CB*CNH*CS*CDH;
  if(which<2){
    float* dst = (which==0)? g_qf : g_kf;
    for(int i=blockIdx.x*blockDim.x+threadIdx.x;i<n;i+=gridDim.x*blockDim.x){
      int d=i&63, s_=(i>>6)&1023, h=(i>>16)&15, b=i>>20;
      float v=src[((size_t)(b*CS+s_))*CH + h*CDH + d];
      float q=rintf(__fmul_rn(clipf(v),s));
      dst[i]=__fdiv_rn(q, s);
    }
  } else {
    for(int i=blockIdx.x*blockDim.x+threadIdx.x;i<n;i+=gridDim.x*blockDim.x){
      int d=i&63, s_=(i>>6)&1023, h=(i>>16)&15, b=i>>20;
      float v=src[((size_t)(b*CS+s_))*CH + h*CDH + d];
      float vc=clipf(v);
      float q=rintf(__fmul_rn(vc,s));
      if(vq_out) vq_out[i]=__fdiv_rn(q, s);
      g_v8t[(((size_t)(b*CNH+h))*CDH+d)*CS + s_]=(int8_t)(int)q;
    }
  }
}

// ---- scores: bit-exact ascending-d fp32 FMA chain (R11 scalar) --------------
__global__ __launch_bounds__(256) void k_scores(const float* __restrict__ mask,
                                                float* __restrict__ ss){
  extern __shared__ float sm[];
  float* qs = sm;             // [64 d][132]
  float* ks = sm + 64*132;    // [64 d][132]
  int rt=blockIdx.x, ct=blockIdx.y, bh=blockIdx.z;
  int b = bh>>4;
  int tid=threadIdx.x, ty=tid>>4, tx=tid&15;
  const float* qg = g_qf + ((size_t)bh*CS + (size_t)rt*128)*CDH;
  const float* kg = g_kf + ((size_t)bh*CS + (size_t)ct*128)*CDH;
  for(int idx=tid; idx<128*16; idx+=256){
    int d4=idx&15, row=idx>>4;
    float4 v = *(const float4*)(qg + (size_t)row*CDH + d4*4);
    qs[(d4*4+0)*132+row]=v.x; qs[(d4*4+1)*132+row]=v.y;
    qs[(d4*4+2)*132+row]=v.z; qs[(d4*4+3)*132+row]=v.w;
    float4 u = *(const float4*)(kg + (size_t)row*CDH + d4*4);
    ks[(d4*4+0)*132+row]=u.x; ks[(d4*4+1)*132+row]=u.y;
    ks[(d4*4+2)*132+row]=u.z; ks[(d4*4+3)*132+row]=u.w;
  }
  __syncthreads();
  float acc[8][8]={};
  for(int d=0; d<64; d++){
    float av[8], bv[8];
    #pragma unroll
    for(int i=0;i<8;i++) av[i]=qs[d*132 + ty*8 + i];
    #pragma unroll
    for(int j=0;j<8;j++) bv[j]=ks[d*132 + tx + 16*j];
    #pragma unroll
    for(int i=0;i<8;i++)
      #pragma unroll
      for(int j=0;j<8;j++) acc[i][j]=__fmaf_rn(av[i],bv[j],acc[i][j]);
  }
  #pragma unroll
  for(int i=0;i<8;i++){
    int row = rt*128 + ty*8 + i;
    #pragma unroll
    for(int j=0;j<8;j++){
      int col = ct*128 + tx + 16*j;
      float sv = __fadd_rn(__fmul_rn(acc[i][j], 0.125f), mask[b*CS+col]);
      ss[((size_t)bh*CS + row)*CS + col] = sv;
    }
  }
}

// ---- softmax per row: reversed block order (L2 reuse), shuffle-tail sums ----
// Sum tree produces bit-identical thread-0 result to the smem tree:
//   level o: v_tid + v_{tid+o} (identical pairings; lanes >= o unused).
__global__ __launch_bounds__(256) void k_softmax(const float* __restrict__ ssrc,
                                                 float* __restrict__ pdst,
                                                 int nrows){
  __shared__ float red[64];     // cross-warp staging (8 warps) + broadcast
  int rowid = nrows - 1 - blockIdx.x;     // reverse: read freshest scores first
  size_t base = (size_t)rowid * CS;
  int tid=threadIdx.x, lane=tid&31, warp=tid>>5;
  float4 x = *(const float4*)(ssrc + base + tid*4);
  // ---- max (order-independent) ----
  float m = fmaxf(fmaxf(x.x,x.y), fmaxf(x.z,x.w));
  #pragma unroll
  for(int o=16;o;o>>=1) m=fmaxf(m,__shfl_xor_sync(0xffffffffu,m,o));
  if(lane==0) red[warp]=m;
  __syncthreads();
  if(tid<8){ float t=red[tid];
    #pragma unroll
    for(int o=4;o;o>>=1) t=fmaxf(t,__shfl_xor_sync(0xffu,t,o));
    red[32+tid]=t; }
  __syncthreads();
  float rowmax = red[32];
  // ---- exp (bit-exact Eigen replica) ----
  float e0=exp_eig(__fsub_rn(x.x,rowmax));
  float e1=exp_eig(__fsub_rn(x.y,rowmax));
  float e2=exp_eig(__fsub_rn(x.z,rowmax));
  float e3=exp_eig(__fsub_rn(x.w,rowmax));
  // ---- sum: same pairwise tree as the passing R11 kernel ----
  // leaf: (e0+e1)+(e2+e3) at index tid; levels o=128..32 need cross-warp.
  float v = ((e0+e1)+(e2+e3));
  // levels o=16..1 within warp FIRST would change pairing order; to keep the
  // exact tree (o=128 first), stage per-thread leaf sums via smem as before
  // but only for levels 128..32, then shuffle for 16..1.
  __shared__ float tree[256];
  tree[tid]=v; __syncthreads();
  if(tid<128) tree[tid]=tree[tid]+tree[tid+128];
  __syncthreads();
  if(tid<64) tree[tid]=tree[tid]+tree[tid+64];
  __syncthreads();
  if(tid<32){
    float t=tree[tid]+tree[tid+32];
    // o=16..1: t_tid + t_{tid+o} — identical pairing to smem tree
    #pragma unroll
    for(int o=16;o;o>>=1) t = t + __shfl_down_sync(0xffffffffu,t,o);
    if(tid==0) red[33]=t;
  }
  __syncthreads();
  float sum = red[33];
  float4 p;
  p.x=__fdiv_rn(e0,sum); p.y=__fdiv_rn(e1,sum);
  p.z=__fdiv_rn(e2,sum); p.w=__fdiv_rn(e3,sum);
  *(float4*)(pdst + base + tid*4) = p;
  if(tid==0) atomicMax(&g_max[7],__float_as_uint(__fdiv_rn(1.f,sum)));
}

// ---- PV (UNCHANGED): context_ = probs_q @ v_q -------------------------------
__global__ __launch_bounds__(256) void k_pv(const float* __restrict__ probs_in,
     float* __restrict__ ctxp, float* __restrict__ ctx){
  __shared__ int ps[128][33];
  __shared__ int vs[64][33];
  int mt=blockIdx.x, bh=blockIdx.y;
  int b=bh>>4, h=bh&15;
  const float* pg = probs_in + (((size_t)bh)*CS + (size_t)mt*128)*CS;
  const int* vtg = (const int*)(g_v8t + (size_t)bh*CDH*CS);
  float sp = __fdiv_rn(127.f, slot_m(7));
  int tid=threadIdx.x, ty=tid>>4, tx=tid&15;
  int acc[8][4]={};
  for(int kc=0;kc<8;kc++){
    for(int idx=tid; idx<128*32; idx+=256){
      int r=idx>>5, w=idx&31;
      float4 p4=*(const float4*)(pg + (size_t)r*CS + kc*128 + w*4);
      int b0=((int)rintf(__fmul_rn(p4.x,sp)))&0xFF;
      int b1=((int)rintf(__fmul_rn(p4.y,sp)))&0xFF;
      int b2=((int)rintf(__fmul_rn(p4.z,sp)))&0xFF;
      int b3=((int)rintf(__fmul_rn(p4.w,sp)))&0xFF;
      ps[r][w]= b0|(b1<<8)|(b2<<16)|(b3<<24);
    }
    for(int idx=tid; idx<64*32; idx+=256){
      int d=idx>>5, w=idx&31;
      vs[d][w]=vtg[(size_t)d*(CS/4)+kc*32+w];
    }
    __syncthreads();
    #pragma unroll
    for(int w=0;w<32;w++){
      int a[8],bb[4];
      #pragma unroll
      for(int i=0;i<8;i++) a[i]=ps[ty*8+i][w];
      #pragma unroll
      for(int j=0;j<4;j++) bb[j]=vs[tx*4+j][w];
      #pragma unroll
      for(int i=0;i<8;i++)
        #pragma unroll
        for(int j=0;j<4;j++) acc[i][j]=__dp4a(a[i],bb[j],acc[i][j]);
    }
    __syncthreads();
  }
  double inv = 1.0/((double)__fdiv_rn(127.f,slot_m(7))*(double)__fdiv_rn(127.f,slot_m(6)));
  #pragma unroll
  for(int i=0;i<8;i++){
    int srow=mt*128+ty*8+i;
    #pragma unroll
    for(int j=0;j<4;j++){
      int d=tx*4+j;
      float c=(float)((double)acc[i][j]*inv);
      if(ctxp) ctxp[(((size_t)bh)*CS+srow)*CDH+d]=c;
      ctx[((size_t)(b*CS+srow))*CH + h*CDH + d]=c;
    }
  }
}

// ---------------- launch ----------------
extern "C" void kernel_launch(void* const* d_in, const int* in_sizes, int n_in,
                              void* d_out, int out_size){
  const float* hs  =(const float*)d_in[0];
  const float* mask=(const float*)d_in[1];
  const float* Wq  =(const float*)d_in[2];
  const float* bq  =(const float*)d_in[3];
  const float* Wk  =(const float*)d_in[4];
  const float* bk  =(const float*)d_in[5];
  const float* Wv  =(const float*)d_in[6];
  const float* bv  =(const float*)d_in[7];
  float* out=(float*)d_out;

  const size_t n_ctx=(size_t)CB*CS*CH;
  const size_t n_sc =(size_t)CB*CNH*CS*CS;
  float *ctx=out, *scores=nullptr, *probs=nullptr, *ctxp=nullptr, *vq=nullptr;
  if((size_t)out_size >= 3*n_ctx + 2*n_sc){
    scores=out+n_ctx; probs=scores+n_sc; ctxp=probs+n_sc; vq=ctxp+n_ctx;
  }
  float* sc_buf = scores;
  float* pr_buf = probs;
  if(!sc_buf){ void* p; cudaGetSymbolAddress(&p, g_sc_fb); sc_buf=(float*)p; }
  if(!pr_buf){ void* p; cudaGetSymbolAddress(&p, g_pr_fb); pr_buf=(float*)p; }

  k_init<<<1,32>>>();
  k_absmax_all<<<dim3(256,4),256>>>(hs,Wq,Wk,Wv);
  k_quant_all<<<dim3(1024,4),256>>>(hs,Wq,Wk,Wv);

  dim3 gg(CM/64, CH/64, 3);
  k_gemm<<<gg,256>>>(bq,bk,bv);

  k_quant_heads_all<<<dim3(1024,3),256>>>(vq);

  const int sc_smem = 64*132*2*sizeof(float);   // 67,584 B
  cudaFuncSetAttribute(k_scores, cudaFuncAttributeMaxDynamicSharedMemorySize, sc_smem);
  k_scores<<<dim3(CS/128,CS/128,CB*CNH),256,sc_smem>>>(mask, sc_buf);

  k_softmax<<<CB*CNH*CS,256>>>(sc_buf, pr_buf, CB*CNH*CS);

  k_pv<<<dim3(CS/128,CB*CNH),256>>>(pr_buf, ctxp, ctx);
}

// round 14
// speedup vs baseline: 1.2456x; 1.1419x over previous
#include <cuda_runtime.h>
#include <cstdint>
#include <math.h>

#define CB 4
#define CS 1024
#define CH 1024
#define CNH 16
#define CDH 64
#define CM (CB*CS)
#define CLIPV 2.5f

// ---------------- scratch (device globals; no allocations allowed) ----------
__device__ unsigned g_max[8];   // 0 hidden,1 Wq,2 Wk,3 Wv,4 q,5 k,6 v,7 probs
__device__ float  g_xd[(size_t)CM*CH];                // dequant hidden (bit-exact)
__device__ float  g_wd[3][(size_t)CH*CH];             // dequant weights (bit-exact)
__device__ float  g_pan[2][3][(size_t)CM*CH];         // per-panel GEMM partials
__device__ float  g_lin[3][(size_t)CM*CH];            // q,k,v fp32 [B,S,H]
__device__ float  g_qf[(size_t)CB*CNH*CS*CDH];        // dequant q [b,h,s,d] fp32
__device__ float  g_kf[(size_t)CB*CNH*CS*CDH];        // dequant k [b,h,s,d] fp32
__device__ int8_t g_v8t[(size_t)CB*CNH*CDH*CS];       // v codes [b,h,d,s]
__device__ float  g_sc_fb[(size_t)CB*CNH*CS*CS];      // fallback scores
__device__ float  g_pr_fb[(size_t)CB*CNH*CS*CS];      // fallback probs

__device__ __forceinline__ float clipf(float v){ return fminf(fmaxf(v,-CLIPV),CLIPV); }
__device__ __forceinline__ float slot_m(int s){ return fmaxf(__uint_as_float(g_max[s]),1e-8f); }

// Eigen pexp<float> replica (unchanged bits).
__device__ __forceinline__ float exp_eig(float x){
  float m = floorf(__fmaf_rn(x, 1.44269504088896341f, 0.5f));
  float r = __fmaf_rn(m, -0.693359375f, x);
  r = __fmaf_rn(m, 2.12194440e-4f, r);
  float r2 = __fmul_rn(r, r);
  float r3 = __fmul_rn(r2, r);
  float y, y1, y2;
  y  = __fmaf_rn(1.9875691500e-4f, r, 1.3981999507e-3f);
  y1 = __fmaf_rn(4.1665795894e-2f, r, 1.6666665459e-1f);
  y2 = __fadd_rn(r, 1.0f);
  y  = __fmaf_rn(y, r, 8.3334519073e-3f);
  y1 = __fmaf_rn(y1, r, 5.0000001201e-1f);
  y  = __fmaf_rn(y, r3, y1);
  y  = __fmaf_rn(y, r2, y2);
  int mi = (int)m;
  return __fmul_rn(y, __int_as_float((mi + 127) << 23));
}

__global__ void k_init(){ if(threadIdx.x<8) g_max[threadIdx.x]=0u; }

// ---- merged abs-max over 4 tensors ------------------------------------------
__global__ void k_absmax_all(const float* __restrict__ hs,
                             const float* __restrict__ Wq,
                             const float* __restrict__ Wk,
                             const float* __restrict__ Wv){
  int slot = blockIdx.y;
  const float* x = (slot==0)? hs : (slot==1)? Wq : (slot==2)? Wk : Wv;
  int n4 = (slot==0)? (CM*CH/4) : (CH*CH/4);
  float m=0.f;
  for (int i=blockIdx.x*blockDim.x+threadIdx.x; i<n4; i+=gridDim.x*blockDim.x){
    float4 v=((const float4*)x)[i];
    m=fmaxf(m,fabsf(clipf(v.x))); m=fmaxf(m,fabsf(clipf(v.y)));
    m=fmaxf(m,fabsf(clipf(v.z))); m=fmaxf(m,fabsf(clipf(v.w)));
  }
  #pragma unroll
  for(int o=16;o;o>>=1) m=fmaxf(m,__shfl_xor_sync(0xffffffffu,m,o));
  if((threadIdx.x&31)==0) atomicMax(&g_max[slot],__float_as_uint(m));
}

// ---- merged dequant of 4 tensors (bit-exact sym_quant fwd value) ------------
__global__ void k_quant_all(const float* __restrict__ hs,
                            const float* __restrict__ Wq,
                            const float* __restrict__ Wk,
                            const float* __restrict__ Wv){
  int slot = blockIdx.y;
  const float* x = (slot==0)? hs : (slot==1)? Wq : (slot==2)? Wk : Wv;
  float* o = (slot==0)? g_xd : g_wd[slot-1];
  int n = (slot==0)? (CM*CH) : (CH*CH);
  float s = __fdiv_rn(127.f, slot_m(slot));
  for(int i=blockIdx.x*blockDim.x+threadIdx.x;i<n;i+=gridDim.x*blockDim.x){
    float q = rintf(__fmul_rn(clipf(x[i]), s));
    o[i] = __fdiv_rn(q, s);
  }
}

// ---- fp32 projection GEMM: one Eigen K=512 panel per block ------------------
// BM=BN=128, BK=16, 256 threads, 8x8 microtile (split fragments at +64).
// Per output element: strictly ascending-k fp32 RN FMA chain from 0 within
// the panel (bit-identical to the previous in-kernel panel accumulation).
// grid: (32, 8, 6) with z = panel*3 + which.
__global__ __launch_bounds__(256) void k_gemm(){
  __shared__ float As[16][132];
  __shared__ float Bs[16][132];
  int which = blockIdx.z % 3, panel = blockIdx.z / 3;
  const float* A = g_xd;
  const float* W = g_wd[which];
  float* C = g_pan[panel][which];
  int bm=blockIdx.x, bn=blockIdx.y;
  int tid=threadIdx.x, ty=tid>>4, tx=tid&15;
  const float* Ab = A + (size_t)bm*128*CH + (size_t)panel*512;
  const float* Wb = W + (size_t)bn*128*CH + (size_t)panel*512;
  int lrow = tid>>1;           // 0..127
  int lk4  = (tid&1)*2;        // 0 or 2
  float4 pa0 = *(const float4*)(Ab + (size_t)lrow*CH + lk4*4);
  float4 pa1 = *(const float4*)(Ab + (size_t)lrow*CH + (lk4+1)*4);
  float4 pb0 = *(const float4*)(Wb + (size_t)lrow*CH + lk4*4);
  float4 pb1 = *(const float4*)(Wb + (size_t)lrow*CH + (lk4+1)*4);
  float acc[8][8]={};
  for(int kt=0;kt<32;kt++){
    __syncthreads();
    As[lk4*4+0][lrow]=pa0.x; As[lk4*4+1][lrow]=pa0.y;
    As[lk4*4+2][lrow]=pa0.z; As[lk4*4+3][lrow]=pa0.w;
    As[(lk4+1)*4+0][lrow]=pa1.x; As[(lk4+1)*4+1][lrow]=pa1.y;
    As[(lk4+1)*4+2][lrow]=pa1.z; As[(lk4+1)*4+3][lrow]=pa1.w;
    Bs[lk4*4+0][lrow]=pb0.x; Bs[lk4*4+1][lrow]=pb0.y;
    Bs[lk4*4+2][lrow]=pb0.z; Bs[lk4*4+3][lrow]=pb0.w;
    Bs[(lk4+1)*4+0][lrow]=pb1.x; Bs[(lk4+1)*4+1][lrow]=pb1.y;
    Bs[(lk4+1)*4+2][lrow]=pb1.z; Bs[(lk4+1)*4+3][lrow]=pb1.w;
    __syncthreads();
    if(kt<31){
      pa0 = *(const float4*)(Ab + (size_t)lrow*CH + (kt+1)*16 + lk4*4);
      pa1 = *(const float4*)(Ab + (size_t)lrow*CH + (kt+1)*16 + (lk4+1)*4);
      pb0 = *(const float4*)(Wb + (size_t)lrow*CH + (kt+1)*16 + lk4*4);
      pb1 = *(const float4*)(Wb + (size_t)lrow*CH + (kt+1)*16 + (lk4+1)*4);
    }
    #pragma unroll
    for(int kk=0;kk<16;kk++){
      float a[8], b[8];
      *(float4*)&a[0] = *(const float4*)&As[kk][ty*4];
      *(float4*)&a[4] = *(const float4*)&As[kk][64+ty*4];
      *(float4*)&b[0] = *(const float4*)&Bs[kk][tx*4];
      *(float4*)&b[4] = *(const float4*)&Bs[kk][64+tx*4];
      #pragma unroll
      for(int i=0;i<8;i++)
        #pragma unroll
        for(int j=0;j<8;j++) acc[i][j]=__fmaf_rn(a[i],b[j],acc[i][j]);
    }
  }
  #pragma unroll
  for(int i=0;i<8;i++){
    int m = bm*128 + ((i<4)? (ty*4+i) : (64+ty*4+i-4));
    float4 c0 = make_float4(acc[i][0],acc[i][1],acc[i][2],acc[i][3]);
    float4 c1 = make_float4(acc[i][4],acc[i][5],acc[i][6],acc[i][7]);
    *(float4*)&C[(size_t)m*CH + bn*128 + tx*4]      = c0;
    *(float4*)&C[(size_t)m*CH + bn*128 + 64 + tx*4] = c1;
  }
}

// ---- combine panels + bias + abs-max (bit-exact old epilogue) ---------------
// c = fadd(fadd(P1, P2), bias)   [old: tot=fadd(0,P1)=P1; c=fadd(fadd(tot,acc),bias)]
__global__ void k_bias_max(const float* __restrict__ bq,
                           const float* __restrict__ bk,
                           const float* __restrict__ bv){
  int which = blockIdx.y;
  const float* bias = (which==0)? bq : (which==1)? bk : bv;
  const float* P1 = g_pan[0][which];
  const float* P2 = g_pan[1][which];
  float* C = g_lin[which];
  const int n = CM*CH;
  float lm=0.f;
  for(int i=blockIdx.x*blockDim.x+threadIdx.x;i<n;i+=gridDim.x*blockDim.x){
    float c = __fadd_rn(__fadd_rn(P1[i], P2[i]), bias[i&(CH-1)]);
    C[i]=c;
    lm=fmaxf(lm,fabsf(clipf(c)));
  }
  #pragma unroll
  for(int o=16;o;o>>=1) lm=fmaxf(lm,__shfl_xor_sync(0xffffffffu,lm,o));
  if((threadIdx.x&31)==0) atomicMax(&g_max[4+which],__float_as_uint(lm));
}

// ---- merged q/k/v re-quantization: grid.y = which (0:q,1:k,2:v) -------------
__global__ void k_quant_heads_all(float* __restrict__ vq_out){
  int which = blockIdx.y;
  const float* src = g_lin[which];
  float s = __fdiv_rn(127.f, slot_m(4+which));
  const int n = CB*CNH*CS*CDH;
  if(which<2){
    float* dst = (which==0)? g_qf : g_kf;
    for(int i=blockIdx.x*blockDim.x+threadIdx.x;i<n;i+=gridDim.x*blockDim.x){
      int d=i&63, s_=(i>>6)&1023, h=(i>>16)&15, b=i>>20;
      float v=src[((size_t)(b*CS+s_))*CH + h*CDH + d];
      float q=rintf(__fmul_rn(clipf(v),s));
      dst[i]=__fdiv_rn(q, s);
    }
  } else {
    for(int i=blockIdx.x*blockDim.x+threadIdx.x;i<n;i+=gridDim.x*blockDim.x){
      int d=i&63, s_=(i>>6)&1023, h=(i>>16)&15, b=i>>20;
      float v=src[((size_t)(b*CS+s_))*CH + h*CDH + d];
      float vc=clipf(v);
      float q=rintf(__fmul_rn(vc,s));
      if(vq_out) vq_out[i]=__fdiv_rn(q, s);
      g_v8t[(((size_t)(b*CNH+h))*CDH+d)*CS + s_]=(int8_t)(int)q;
    }
  }
}

// ---- scores: bit-exact ascending-d fp32 FMA chain (unchanged) ---------------
__global__ __launch_bounds__(256) void k_scores(const float* __restrict__ mask,
                                                float* __restrict__ ss){
  extern __shared__ float sm[];
  float* qs = sm;             // [64 d][132]
  float* ks = sm + 64*132;    // [64 d][132]
  int rt=blockIdx.x, ct=blockIdx.y, bh=blockIdx.z;
  int b = bh>>4;
  int tid=threadIdx.x, ty=tid>>4, tx=tid&15;
  const float* qg = g_qf + ((size_t)bh*CS + (size_t)rt*128)*CDH;
  const float* kg = g_kf + ((size_t)bh*CS + (size_t)ct*128)*CDH;
  for(int idx=tid; idx<128*16; idx+=256){
    int d4=idx&15, row=idx>>4;
    float4 v = *(const float4*)(qg + (size_t)row*CDH + d4*4);
    qs[(d4*4+0)*132+row]=v.x; qs[(d4*4+1)*132+row]=v.y;
    qs[(d4*4+2)*132+row]=v.z; qs[(d4*4+3)*132+row]=v.w;
    float4 u = *(const float4*)(kg + (size_t)row*CDH + d4*4);
    ks[(d4*4+0)*132+row]=u.x; ks[(d4*4+1)*132+row]=u.y;
    ks[(d4*4+2)*132+row]=u.z; ks[(d4*4+3)*132+row]=u.w;
  }
  __syncthreads();
  float acc[8][8]={};
  for(int d=0; d<64; d++){
    float av[8], bv[8];
    #pragma unroll
    for(int i=0;i<8;i++) av[i]=qs[d*132 + ty*8 + i];
    #pragma unroll
    for(int j=0;j<8;j++) bv[j]=ks[d*132 + tx + 16*j];
    #pragma unroll
    for(int i=0;i<8;i++)
      #pragma unroll
      for(int j=0;j<8;j++) acc[i][j]=__fmaf_rn(av[i],bv[j],acc[i][j]);
  }
  #pragma unroll
  for(int i=0;i<8;i++){
    int row = rt*128 + ty*8 + i;
    #pragma unroll
    for(int j=0;j<8;j++){
      int col = ct*128 + tx + 16*j;
      float sv = __fadd_rn(__fmul_rn(acc[i][j], 0.125f), mask[b*CS+col]);
      ss[((size_t)bh*CS + row)*CS + col] = sv;
    }
  }
}

// ---- softmax per row (unchanged bits from R13) -------------------------------
__global__ __launch_bounds__(256) void k_softmax(const float* __restrict__ ssrc,
                                                 float* __restrict__ pdst,
                                                 int nrows){
  __shared__ float red[64];
  int rowid = nrows - 1 - blockIdx.x;
  size_t base = (size_t)rowid * CS;
  int tid=threadIdx.x, lane=tid&31, warp=tid>>5;
  float4 x = *(const float4*)(ssrc + base + tid*4);
  float m = fmaxf(fmaxf(x.x,x.y), fmaxf(x.z,x.w));
  #pragma unroll
  for(int o=16;o;o>>=1) m=fmaxf(m,__shfl_xor_sync(0xffffffffu,m,o));
  if(lane==0) red[warp]=m;
  __syncthreads();
  if(tid<8){ float t=red[tid];
    #pragma unroll
    for(int o=4;o;o>>=1) t=fmaxf(t,__shfl_xor_sync(0xffu,t,o));
    red[32+tid]=t; }
  __syncthreads();
  float rowmax = red[32];
  float e0=exp_eig(__fsub_rn(x.x,rowmax));
  float e1=exp_eig(__fsub_rn(x.y,rowmax));
  float e2=exp_eig(__fsub_rn(x.z,rowmax));
  float e3=exp_eig(__fsub_rn(x.w,rowmax));
  float v = ((e0+e1)+(e2+e3));
  __shared__ float tree[256];
  tree[tid]=v; __syncthreads();
  if(tid<128) tree[tid]=tree[tid]+tree[tid+128];
  __syncthreads();
  if(tid<64) tree[tid]=tree[tid]+tree[tid+64];
  __syncthreads();
  if(tid<32){
    float t=tree[tid]+tree[tid+32];
    #pragma unroll
    for(int o=16;o;o>>=1) t = t + __shfl_down_sync(0xffffffffu,t,o);
    if(tid==0) red[33]=t;
  }
  __syncthreads();
  float sum = red[33];
  float4 p;
  p.x=__fdiv_rn(e0,sum); p.y=__fdiv_rn(e1,sum);
  p.z=__fdiv_rn(e2,sum); p.w=__fdiv_rn(e3,sum);
  *(float4*)(pdst + base + tid*4) = p;
  if(tid==0) atomicMax(&g_max[7],__float_as_uint(__fdiv_rn(1.f,sum)));
}

// ---- PV (unchanged): context_ = probs_q @ v_q -------------------------------
__global__ __launch_bounds__(256) void k_pv(const float* __restrict__ probs_in,
     float* __restrict__ ctxp, float* __restrict__ ctx){
  __shared__ int ps[128][33];
  __shared__ int vs[64][33];
  int mt=blockIdx.x, bh=blockIdx.y;
  int b=bh>>4, h=bh&15;
  const float* pg = probs_in + (((size_t)bh)*CS + (size_t)mt*128)*CS;
  const int* vtg = (const int*)(g_v8t + (size_t)bh*CDH*CS);
  float sp = __fdiv_rn(127.f, slot_m(7));
  int tid=threadIdx.x, ty=tid>>4, tx=tid&15;
  int acc[8][4]={};
  for(int kc=0;kc<8;kc++){
    for(int idx=tid; idx<128*32; idx+=256){
      int r=idx>>5, w=idx&31;
      float4 p4=*(const float4*)(pg + (size_t)r*CS + kc*128 + w*4);
      int b0=((int)rintf(__fmul_rn(p4.x,sp)))&0xFF;
      int b1=((int)rintf(__fmul_rn(p4.y,sp)))&0xFF;
      int b2=((int)rintf(__fmul_rn(p4.z,sp)))&0xFF;
      int b3=((int)rintf(__fmul_rn(p4.w,sp)))&0xFF;
      ps[r][w]= b0|(b1<<8)|(b2<<16)|(b3<<24);
    }
    for(int idx=tid; idx<64*32; idx+=256){
      int d=idx>>5, w=idx&31;
      vs[d][w]=vtg[(size_t)d*(CS/4)+kc*32+w];
    }
    __syncthreads();
    #pragma unroll
    for(int w=0;w<32;w++){
      int a[8],bb[4];
      #pragma unroll
      for(int i=0;i<8;i++) a[i]=ps[ty*8+i][w];
      #pragma unroll
      for(int j=0;j<4;j++) bb[j]=vs[tx*4+j][w];
      #pragma unroll
      for(int i=0;i<8;i++)
        #pragma unroll
        for(int j=0;j<4;j++) acc[i][j]=__dp4a(a[i],bb[j],acc[i][j]);
    }
    __syncthreads();
  }
  double inv = 1.0/((double)__fdiv_rn(127.f,slot_m(7))*(double)__fdiv_rn(127.f,slot_m(6)));
  #pragma unroll
  for(int i=0;i<8;i++){
    int srow=mt*128+ty*8+i;
    #pragma unroll
    for(int j=0;j<4;j++){
      int d=tx*4+j;
      float c=(float)((double)acc[i][j]*inv);
      if(ctxp) ctxp[(((size_t)bh)*CS+srow)*CDH+d]=c;
      ctx[((size_t)(b*CS+srow))*CH + h*CDH + d]=c;
    }
  }
}

// ---------------- launch ----------------
extern "C" void kernel_launch(void* const* d_in, const int* in_sizes, int n_in,
                              void* d_out, int out_size){
  const float* hs  =(const float*)d_in[0];
  const float* mask=(const float*)d_in[1];
  const float* Wq  =(const float*)d_in[2];
  const float* bq  =(const float*)d_in[3];
  const float* Wk  =(const float*)d_in[4];
  const float* bk  =(const float*)d_in[5];
  const float* Wv  =(const float*)d_in[6];
  const float* bv  =(const float*)d_in[7];
  float* out=(float*)d_out;

  const size_t n_ctx=(size_t)CB*CS*CH;
  const size_t n_sc =(size_t)CB*CNH*CS*CS;
  float *ctx=out, *scores=nullptr, *probs=nullptr, *ctxp=nullptr, *vq=nullptr;
  if((size_t)out_size >= 3*n_ctx + 2*n_sc){
    scores=out+n_ctx; probs=scores+n_sc; ctxp=probs+n_sc; vq=ctxp+n_ctx;
  }
  float* sc_buf = scores;
  float* pr_buf = probs;
  if(!sc_buf){ void* p; cudaGetSymbolAddress(&p, g_sc_fb); sc_buf=(float*)p; }
  if(!pr_buf){ void* p; cudaGetSymbolAddress(&p, g_pr_fb); pr_buf=(float*)p; }

  k_init<<<1,32>>>();
  k_absmax_all<<<dim3(256,4),256>>>(hs,Wq,Wk,Wv);
  k_quant_all<<<dim3(1024,4),256>>>(hs,Wq,Wk,Wv);

  k_gemm<<<dim3(CM/128, CH/128, 6),256>>>();
  k_bias_max<<<dim3(2048,3),256>>>(bq,bk,bv);

  k_quant_heads_all<<<dim3(1024,3),256>>>(vq);

  const int sc_smem = 64*132*2*sizeof(float);   // 67,584 B
  cudaFuncSetAttribute(k_scores, cudaFuncAttributeMaxDynamicSharedMemorySize, sc_smem);
  k_scores<<<dim3(CS/128,CS/128,CB*CNH),256,sc_smem>>>(mask, sc_buf);

  k_softmax<<<CB*CNH*CS,256>>>(sc_buf, pr_buf, CB*CNH*CS);

  k_pv<<<dim3(CS/128,CB*CNH),256>>>(pr_buf, ctxp, ctx);
}

// round 15
// speedup vs baseline: 1.2528x; 1.0058x over previous
#include <cuda_runtime.h>
#include <cstdint>
#include <math.h>

#define CB 4
#define CS 1024
#define CH 1024
#define CNH 16
#define CDH 64
#define CM (CB*CS)
#define CLIPV 2.5f

// ---------------- scratch (device globals; no allocations allowed) ----------
__device__ unsigned g_max[8];   // 0 hidden,1 Wq,2 Wk,3 Wv,4 q,5 k,6 v,7 probs
__device__ float  g_xd[(size_t)CM*CH];                // dequant hidden (bit-exact)
__device__ float  g_wd[3][(size_t)CH*CH];             // dequant weights (bit-exact)
__device__ float  g_pan[2][3][(size_t)CM*CH];         // per-panel GEMM partials
__device__ float  g_lin[3][(size_t)CM*CH];            // q,k,v fp32 [B,S,H]
__device__ float  g_qf[(size_t)CB*CNH*CS*CDH];        // dequant q [b,h,s,d] fp32
__device__ float  g_kf[(size_t)CB*CNH*CS*CDH];        // dequant k [b,h,s,d] fp32
__device__ int8_t g_v8t[(size_t)CB*CNH*CDH*CS];       // v codes [b,h,d,s]
__device__ float  g_sc_fb[(size_t)CB*CNH*CS*CS];      // fallback scores
__device__ float  g_pr_fb[(size_t)CB*CNH*CS*CS];      // fallback probs

__device__ __forceinline__ float clipf(float v){ return fminf(fmaxf(v,-CLIPV),CLIPV); }
__device__ __forceinline__ float slot_m(int s){ return fmaxf(__uint_as_float(g_max[s]),1e-8f); }

// Eigen pexp<float> replica (unchanged bits).
__device__ __forceinline__ float exp_eig(float x){
  float m = floorf(__fmaf_rn(x, 1.44269504088896341f, 0.5f));
  float r = __fmaf_rn(m, -0.693359375f, x);
  r = __fmaf_rn(m, 2.12194440e-4f, r);
  float r2 = __fmul_rn(r, r);
  float r3 = __fmul_rn(r2, r);
  float y, y1, y2;
  y  = __fmaf_rn(1.9875691500e-4f, r, 1.3981999507e-3f);
  y1 = __fmaf_rn(4.1665795894e-2f, r, 1.6666665459e-1f);
  y2 = __fadd_rn(r, 1.0f);
  y  = __fmaf_rn(y, r, 8.3334519073e-3f);
  y1 = __fmaf_rn(y1, r, 5.0000001201e-1f);
  y  = __fmaf_rn(y, r3, y1);
  y  = __fmaf_rn(y, r2, y2);
  int mi = (int)m;
  return __fmul_rn(y, __int_as_float((mi + 127) << 23));
}

__global__ void k_init(){ if(threadIdx.x<8) g_max[threadIdx.x]=0u; }

// ---- merged abs-max over 4 tensors ------------------------------------------
__global__ void k_absmax_all(const float* __restrict__ hs,
                             const float* __restrict__ Wq,
                             const float* __restrict__ Wk,
                             const float* __restrict__ Wv){
  int slot = blockIdx.y;
  const float* x = (slot==0)? hs : (slot==1)? Wq : (slot==2)? Wk : Wv;
  int n4 = (slot==0)? (CM*CH/4) : (CH*CH/4);
  float m=0.f;
  for (int i=blockIdx.x*blockDim.x+threadIdx.x; i<n4; i+=gridDim.x*blockDim.x){
    float4 v=((const float4*)x)[i];
    m=fmaxf(m,fabsf(clipf(v.x))); m=fmaxf(m,fabsf(clipf(v.y)));
    m=fmaxf(m,fabsf(clipf(v.z))); m=fmaxf(m,fabsf(clipf(v.w)));
  }
  #pragma unroll
  for(int o=16;o;o>>=1) m=fmaxf(m,__shfl_xor_sync(0xffffffffu,m,o));
  if((threadIdx.x&31)==0) atomicMax(&g_max[slot],__float_as_uint(m));
}

// ---- merged dequant of 4 tensors (bit-exact sym_quant fwd value) ------------
__global__ void k_quant_all(const float* __restrict__ hs,
                            const float* __restrict__ Wq,
                            const float* __restrict__ Wk,
                            const float* __restrict__ Wv){
  int slot = blockIdx.y;
  const float* x = (slot==0)? hs : (slot==1)? Wq : (slot==2)? Wk : Wv;
  float* o = (slot==0)? g_xd : g_wd[slot-1];
  int n = (slot==0)? (CM*CH) : (CH*CH);
  float s = __fdiv_rn(127.f, slot_m(slot));
  for(int i=blockIdx.x*blockDim.x+threadIdx.x;i<n;i+=gridDim.x*blockDim.x){
    float q = rintf(__fmul_rn(clipf(x[i]), s));
    o[i] = __fdiv_rn(q, s);
  }
}

// ---- fp32 projection GEMM: one Eigen K=512 panel per block ------------------
// BM=BN=128, BK=16, 256 threads, 8x8 microtile (split fragments at +64),
// double-buffered smem: ONE barrier per k-tile.
// Per output element: strictly ascending-k fp32 RN FMA chain from 0 within
// the panel (bit-identical). grid: (32, 8, 6), z = panel*3 + which.
__global__ __launch_bounds__(256) void k_gemm(){
  __shared__ float As[2][16][132];
  __shared__ float Bs[2][16][132];
  int which = blockIdx.z % 3, panel = blockIdx.z / 3;
  const float* A = g_xd;
  const float* W = g_wd[which];
  float* C = g_pan[panel][which];
  int bm=blockIdx.x, bn=blockIdx.y;
  int tid=threadIdx.x, ty=tid>>4, tx=tid&15;
  const float* Ab = A + (size_t)bm*128*CH + (size_t)panel*512;
  const float* Wb = W + (size_t)bn*128*CH + (size_t)panel*512;
  int lrow = tid>>1;           // 0..127
  int lk4  = (tid&1)*2;        // 0 or 2
  float4 pa0 = *(const float4*)(Ab + (size_t)lrow*CH + lk4*4);
  float4 pa1 = *(const float4*)(Ab + (size_t)lrow*CH + (lk4+1)*4);
  float4 pb0 = *(const float4*)(Wb + (size_t)lrow*CH + lk4*4);
  float4 pb1 = *(const float4*)(Wb + (size_t)lrow*CH + (lk4+1)*4);
  // stage tile 0 into buffer 0
  As[0][lk4*4+0][lrow]=pa0.x; As[0][lk4*4+1][lrow]=pa0.y;
  As[0][lk4*4+2][lrow]=pa0.z; As[0][lk4*4+3][lrow]=pa0.w;
  As[0][(lk4+1)*4+0][lrow]=pa1.x; As[0][(lk4+1)*4+1][lrow]=pa1.y;
  As[0][(lk4+1)*4+2][lrow]=pa1.z; As[0][(lk4+1)*4+3][lrow]=pa1.w;
  Bs[0][lk4*4+0][lrow]=pb0.x; Bs[0][lk4*4+1][lrow]=pb0.y;
  Bs[0][lk4*4+2][lrow]=pb0.z; Bs[0][lk4*4+3][lrow]=pb0.w;
  Bs[0][(lk4+1)*4+0][lrow]=pb1.x; Bs[0][(lk4+1)*4+1][lrow]=pb1.y;
  Bs[0][(lk4+1)*4+2][lrow]=pb1.z; Bs[0][(lk4+1)*4+3][lrow]=pb1.w;
  __syncthreads();
  float acc[8][8]={};
  for(int kt=0;kt<32;kt++){
    int cur=kt&1, nxt=cur^1;
    if(kt<31){
      pa0 = *(const float4*)(Ab + (size_t)lrow*CH + (kt+1)*16 + lk4*4);
      pa1 = *(const float4*)(Ab + (size_t)lrow*CH + (kt+1)*16 + (lk4+1)*4);
      pb0 = *(const float4*)(Wb + (size_t)lrow*CH + (kt+1)*16 + lk4*4);
      pb1 = *(const float4*)(Wb + (size_t)lrow*CH + (kt+1)*16 + (lk4+1)*4);
    }
    #pragma unroll
    for(int kk=0;kk<16;kk++){
      float a[8], b[8];
      *(float4*)&a[0] = *(const float4*)&As[cur][kk][ty*4];
      *(float4*)&a[4] = *(const float4*)&As[cur][kk][64+ty*4];
      *(float4*)&b[0] = *(const float4*)&Bs[cur][kk][tx*4];
      *(float4*)&b[4] = *(const float4*)&Bs[cur][kk][64+tx*4];
      #pragma unroll
      for(int i=0;i<8;i++)
        #pragma unroll
        for(int j=0;j<8;j++) acc[i][j]=__fmaf_rn(a[i],b[j],acc[i][j]);
    }
    if(kt<31){
      As[nxt][lk4*4+0][lrow]=pa0.x; As[nxt][lk4*4+1][lrow]=pa0.y;
      As[nxt][lk4*4+2][lrow]=pa0.z; As[nxt][lk4*4+3][lrow]=pa0.w;
      As[nxt][(lk4+1)*4+0][lrow]=pa1.x; As[nxt][(lk4+1)*4+1][lrow]=pa1.y;
      As[nxt][(lk4+1)*4+2][lrow]=pa1.z; As[nxt][(lk4+1)*4+3][lrow]=pa1.w;
      Bs[nxt][lk4*4+0][lrow]=pb0.x; Bs[nxt][lk4*4+1][lrow]=pb0.y;
      Bs[nxt][lk4*4+2][lrow]=pb0.z; Bs[nxt][lk4*4+3][lrow]=pb0.w;
      Bs[nxt][(lk4+1)*4+0][lrow]=pb1.x; Bs[nxt][(lk4+1)*4+1][lrow]=pb1.y;
      Bs[nxt][(lk4+1)*4+2][lrow]=pb1.z; Bs[nxt][(lk4+1)*4+3][lrow]=pb1.w;
      __syncthreads();
    }
  }
  #pragma unroll
  for(int i=0;i<8;i++){
    int m = bm*128 + ((i<4)? (ty*4+i) : (64+ty*4+i-4));
    float4 c0 = make_float4(acc[i][0],acc[i][1],acc[i][2],acc[i][3]);
    float4 c1 = make_float4(acc[i][4],acc[i][5],acc[i][6],acc[i][7]);
    *(float4*)&C[(size_t)m*CH + bn*128 + tx*4]      = c0;
    *(float4*)&C[(size_t)m*CH + bn*128 + 64 + tx*4] = c1;
  }
}

// ---- combine panels + bias + abs-max (bit-exact old epilogue) ---------------
__global__ void k_bias_max(const float* __restrict__ bq,
                           const float* __restrict__ bk,
                           const float* __restrict__ bv){
  int which = blockIdx.y;
  const float* bias = (which==0)? bq : (which==1)? bk : bv;
  const float* P1 = g_pan[0][which];
  const float* P2 = g_pan[1][which];
  float* C = g_lin[which];
  const int n = CM*CH;
  float lm=0.f;
  for(int i=blockIdx.x*blockDim.x+threadIdx.x;i<n;i+=gridDim.x*blockDim.x){
    float c = __fadd_rn(__fadd_rn(P1[i], P2[i]), bias[i&(CH-1)]);
    C[i]=c;
    lm=fmaxf(lm,fabsf(clipf(c)));
  }
  #pragma unroll
  for(int o=16;o;o>>=1) lm=fmaxf(lm,__shfl_xor_sync(0xffffffffu,lm,o));
  if((threadIdx.x&31)==0) atomicMax(&g_max[4+which],__float_as_uint(lm));
}

// ---- merged q/k/v re-quantization: grid.y = which (0:q,1:k,2:v) -------------
__global__ void k_quant_heads_all(float* __restrict__ vq_out){
  int which = blockIdx.y;
  const float* src = g_lin[which];
  float s = __fdiv_rn(127.f, slot_m(4+which));
  const int n = CB*CNH*CS*CDH;
  if(which<2){
    float* dst = (which==0)? g_qf : g_kf;
    for(int i=blockIdx.x*blockDim.x+threadIdx.x;i<n;i+=gridDim.x*blockDim.x){
      int d=i&63, s_=(i>>6)&1023, h=(i>>16)&15, b=i>>20;
      float v=src[((size_t)(b*CS+s_))*CH + h*CDH + d];
      float q=rintf(__fmul_rn(clipf(v),s));
      dst[i]=__fdiv_rn(q, s);
    }
  } else {
    for(int i=blockIdx.x*blockDim.x+threadIdx.x;i<n;i+=gridDim.x*blockDim.x){
      int d=i&63, s_=(i>>6)&1023, h=(i>>16)&15, b=i>>20;
      float v=src[((size_t)(b*CS+s_))*CH + h*CDH + d];
      float vc=clipf(v);
      float q=rintf(__fmul_rn(vc,s));
      if(vq_out) vq_out[i]=__fdiv_rn(q, s);
      g_v8t[(((size_t)(b*CNH+h))*CDH+d)*CS + s_]=(int8_t)(int)q;
    }
  }
}

// ---- scores: bit-exact ascending-d fp32 FMA chain, split-fragment 8x8 -------
// Values and destinations identical to previous version; only the thread->
// element mapping changed (vectorized LDS.128 fragment reads).
__global__ __launch_bounds__(256) void k_scores(const float* __restrict__ mask,
                                                float* __restrict__ ss){
  extern __shared__ float sm[];
  float* qs = sm;             // [64 d][132]
  float* ks = sm + 64*132;    // [64 d][132]
  int rt=blockIdx.x, ct=blockIdx.y, bh=blockIdx.z;
  int b = bh>>4;
  int tid=threadIdx.x, ty=tid>>4, tx=tid&15;
  const float* qg = g_qf + ((size_t)bh*CS + (size_t)rt*128)*CDH;
  const float* kg = g_kf + ((size_t)bh*CS + (size_t)ct*128)*CDH;
  for(int idx=tid; idx<128*16; idx+=256){
    int d4=idx&15, row=idx>>4;
    float4 v = *(const float4*)(qg + (size_t)row*CDH + d4*4);
    qs[(d4*4+0)*132+row]=v.x; qs[(d4*4+1)*132+row]=v.y;
    qs[(d4*4+2)*132+row]=v.z; qs[(d4*4+3)*132+row]=v.w;
    float4 u = *(const float4*)(kg + (size_t)row*CDH + d4*4);
    ks[(d4*4+0)*132+row]=u.x; ks[(d4*4+1)*132+row]=u.y;
    ks[(d4*4+2)*132+row]=u.z; ks[(d4*4+3)*132+row]=u.w;
  }
  __syncthreads();
  float acc[8][8]={};
  for(int d=0; d<64; d++){               // ascending-d chain per element
    float a[8], bv[8];
    *(float4*)&a[0]  = *(const float4*)&qs[d*132 + ty*4];
    *(float4*)&a[4]  = *(const float4*)&qs[d*132 + 64 + ty*4];
    *(float4*)&bv[0] = *(const float4*)&ks[d*132 + tx*4];
    *(float4*)&bv[4] = *(const float4*)&ks[d*132 + 64 + tx*4];
    #pragma unroll
    for(int i=0;i<8;i++)
      #pragma unroll
      for(int j=0;j<8;j++) acc[i][j]=__fmaf_rn(a[i],bv[j],acc[i][j]);
  }
  #pragma unroll
  for(int i=0;i<8;i++){
    int row = rt*128 + ((i<4)? (ty*4+i) : (64+ty*4+i-4));
    #pragma unroll
    for(int jh=0;jh<2;jh++){
      int col0 = ct*128 + ((jh==0)? (tx*4) : (64+tx*4));
      float4 sv;
      sv.x = __fadd_rn(__fmul_rn(acc[i][jh*4+0], 0.125f), mask[b*CS+col0+0]);
      sv.y = __fadd_rn(__fmul_rn(acc[i][jh*4+1], 0.125f), mask[b*CS+col0+1]);
      sv.z = __fadd_rn(__fmul_rn(acc[i][jh*4+2], 0.125f), mask[b*CS+col0+2]);
      sv.w = __fadd_rn(__fmul_rn(acc[i][jh*4+3], 0.125f), mask[b*CS+col0+3]);
      *(float4*)&ss[((size_t)bh*CS + row)*CS + col0] = sv;
    }
  }
}

// ---- softmax per row (unchanged bits) ----------------------------------------
__global__ __launch_bounds__(256) void k_softmax(const float* __restrict__ ssrc,
                                                 float* __restrict__ pdst,
                                                 int nrows){
  __shared__ float red[64];
  int rowid = nrows - 1 - blockIdx.x;
  size_t base = (size_t)rowid * CS;
  int tid=threadIdx.x, lane=tid&31, warp=tid>>5;
  float4 x = *(const float4*)(ssrc + base + tid*4);
  float m = fmaxf(fmaxf(x.x,x.y), fmaxf(x.z,x.w));
  #pragma unroll
  for(int o=16;o;o>>=1) m=fmaxf(m,__shfl_xor_sync(0xffffffffu,m,o));
  if(lane==0) red[warp]=m;
  __syncthreads();
  if(tid<8){ float t=red[tid];
    #pragma unroll
    for(int o=4;o;o>>=1) t=fmaxf(t,__shfl_xor_sync(0xffu,t,o));
    red[32+tid]=t; }
  __syncthreads();
  float rowmax = red[32];
  float e0=exp_eig(__fsub_rn(x.x,rowmax));
  float e1=exp_eig(__fsub_rn(x.y,rowmax));
  float e2=exp_eig(__fsub_rn(x.z,rowmax));
  float e3=exp_eig(__fsub_rn(x.w,rowmax));
  float v = ((e0+e1)+(e2+e3));
  __shared__ float tree[256];
  tree[tid]=v; __syncthreads();
  if(tid<128) tree[tid]=tree[tid]+tree[tid+128];
  __syncthreads();
  if(tid<64) tree[tid]=tree[tid]+tree[tid+64];
  __syncthreads();
  if(tid<32){
    float t=tree[tid]+tree[tid+32];
    #pragma unroll
    for(int o=16;o;o>>=1) t = t + __shfl_down_sync(0xffffffffu,t,o);
    if(tid==0) red[33]=t;
  }
  __syncthreads();
  float sum = red[33];
  float4 p;
  p.x=__fdiv_rn(e0,sum); p.y=__fdiv_rn(e1,sum);
  p.z=__fdiv_rn(e2,sum); p.w=__fdiv_rn(e3,sum);
  *(float4*)(pdst + base + tid*4) = p;
  if(tid==0) atomicMax(&g_max[7],__float_as_uint(__fdiv_rn(1.f,sum)));
}

// ---- PV (unchanged): context_ = probs_q @ v_q -------------------------------
__global__ __launch_bounds__(256) void k_pv(const float* __restrict__ probs_in,
     float* __restrict__ ctxp, float* __restrict__ ctx){
  __shared__ int ps[128][33];
  __shared__ int vs[64][33];
  int mt=blockIdx.x, bh=blockIdx.y;
  int b=bh>>4, h=bh&15;
  const float* pg = probs_in + (((size_t)bh)*CS + (size_t)mt*128)*CS;
  const int* vtg = (const int*)(g_v8t + (size_t)bh*CDH*CS);
  float sp = __fdiv_rn(127.f, slot_m(7));
  int tid=threadIdx.x, ty=tid>>4, tx=tid&15;
  int acc[8][4]={};
  for(int kc=0;kc<8;kc++){
    for(int idx=tid; idx<128*32; idx+=256){
      int r=idx>>5, w=idx&31;
      float4 p4=*(const float4*)(pg + (size_t)r*CS + kc*128 + w*4);
      int b0=((int)rintf(__fmul_rn(p4.x,sp)))&0xFF;
      int b1=((int)rintf(__fmul_rn(p4.y,sp)))&0xFF;
      int b2=((int)rintf(__fmul_rn(p4.z,sp)))&0xFF;
      int b3=((int)rintf(__fmul_rn(p4.w,sp)))&0xFF;
      ps[r][w]= b0|(b1<<8)|(b2<<16)|(b3<<24);
    }
    for(int idx=tid; idx<64*32; idx+=256){
      int d=idx>>5, w=idx&31;
      vs[d][w]=vtg[(size_t)d*(CS/4)+kc*32+w];
    }
    __syncthreads();
    #pragma unroll
    for(int w=0;w<32;w++){
      int a[8],bb[4];
      #pragma unroll
      for(int i=0;i<8;i++) a[i]=ps[ty*8+i][w];
      #pragma unroll
      for(int j=0;j<4;j++) bb[j]=vs[tx*4+j][w];
      #pragma unroll
      for(int i=0;i<8;i++)
        #pragma unroll
        for(int j=0;j<4;j++) acc[i][j]=__dp4a(a[i],bb[j],acc[i][j]);
    }
    __syncthreads();
  }
  double inv = 1.0/((double)__fdiv_rn(127.f,slot_m(7))*(double)__fdiv_rn(127.f,slot_m(6)));
  #pragma unroll
  for(int i=0;i<8;i++){
    int srow=mt*128+ty*8+i;
    #pragma unroll
    for(int j=0;j<4;j++){
      int d=tx*4+j;
      float c=(float)((double)acc[i][j]*inv);
      if(ctxp) ctxp[(((size_t)bh)*CS+srow)*CDH+d]=c;
      ctx[((size_t)(b*CS+srow))*CH + h*CDH + d]=c;
    }
  }
}

// ---------------- launch ----------------
extern "C" void kernel_launch(void* const* d_in, const int* in_sizes, int n_in,
                              void* d_out, int out_size){
  const float* hs  =(const float*)d_in[0];
  const float* mask=(const float*)d_in[1];
  const float* Wq  =(const float*)d_in[2];
  const float* bq  =(const float*)d_in[3];
  const float* Wk  =(const float*)d_in[4];
  const float* bk  =(const float*)d_in[5];
  const float* Wv  =(const float*)d_in[6];
  const float* bv  =(const float*)d_in[7];
  float* out=(float*)d_out;

  const size_t n_ctx=(size_t)CB*CS*CH;
  const size_t n_sc =(size_t)CB*CNH*CS*CS;
  float *ctx=out, *scores=nullptr, *probs=nullptr, *ctxp=nullptr, *vq=nullptr;
  if((size_t)out_size >= 3*n_ctx + 2*n_sc){
    scores=out+n_ctx; probs=scores+n_sc; ctxp=probs+n_sc; vq=ctxp+n_ctx;
  }
  float* sc_buf = scores;
  float* pr_buf = probs;
  if(!sc_buf){ void* p; cudaGetSymbolAddress(&p, g_sc_fb); sc_buf=(float*)p; }
  if(!pr_buf){ void* p; cudaGetSymbolAddress(&p, g_pr_fb); pr_buf=(float*)p; }

  k_init<<<1,32>>>();
  k_absmax_all<<<dim3(256,4),256>>>(hs,Wq,Wk,Wv);
  k_quant_all<<<dim3(1024,4),256>>>(hs,Wq,Wk,Wv);

  k_gemm<<<dim3(CM/128, CH/128, 6),256>>>();
  k_bias_max<<<dim3(2048,3),256>>>(bq,bk,bv);

  k_quant_heads_all<<<dim3(1024,3),256>>>(vq);

  const int sc_smem = 64*132*2*sizeof(float);   // 67,584 B
  cudaFuncSetAttribute(k_scores, cudaFuncAttributeMaxDynamicSharedMemorySize, sc_smem);
  k_scores<<<dim3(CS/128,CS/128,CB*CNH),256,sc_smem>>>(mask, sc_buf);

  k_softmax<<<CB*CNH*CS,256>>>(sc_buf, pr_buf, CB*CNH*CS);

  k_pv<<<dim3(CS/128,CB*CNH),256>>>(pr_buf, ctxp, ctx);
}

// round 16
// speedup vs baseline: 1.3201x; 1.0537x over previous
#include <cuda_runtime.h>
#include <cstdint>
#include <math.h>

#define CB 4
#define CS 1024
#define CH 1024
#define CNH 16
#define CDH 64
#define CM (CB*CS)
#define CLIPV 2.5f

// ---------------- scratch (device globals; no allocations allowed) ----------
__device__ unsigned g_max[8];   // 0 hidden,1 Wq,2 Wk,3 Wv,4 q,5 k,6 v,7 probs
__device__ float  g_xd[(size_t)CM*CH];                // dequant hidden (bit-exact)
__device__ float  g_wd[3][(size_t)CH*CH];             // dequant weights (bit-exact)
__device__ float  g_pan[2][3][(size_t)CM*CH];         // per-panel GEMM partials
__device__ float  g_lin[3][(size_t)CM*CH];            // q,k,v fp32 [B,S,H]
__device__ float  g_qf[(size_t)CB*CNH*CS*CDH];        // dequant q [b,h,s,d] fp32
__device__ float  g_kf[(size_t)CB*CNH*CS*CDH];        // dequant k [b,h,s,d] fp32
__device__ int8_t g_v8t[(size_t)CB*CNH*CDH*CS];       // v codes [b,h,d,s]
__device__ float  g_sc_fb[(size_t)CB*CNH*CS*CS];      // fallback scores
__device__ float  g_pr_fb[(size_t)CB*CNH*CS*CS];      // fallback probs

__device__ __forceinline__ float clipf(float v){ return fminf(fmaxf(v,-CLIPV),CLIPV); }
__device__ __forceinline__ float slot_m(int s){ return fmaxf(__uint_as_float(g_max[s]),1e-8f); }

// Eigen pexp<float> replica (unchanged bits).
__device__ __forceinline__ float exp_eig(float x){
  float m = floorf(__fmaf_rn(x, 1.44269504088896341f, 0.5f));
  float r = __fmaf_rn(m, -0.693359375f, x);
  r = __fmaf_rn(m, 2.12194440e-4f, r);
  float r2 = __fmul_rn(r, r);
  float r3 = __fmul_rn(r2, r);
  float y, y1, y2;
  y  = __fmaf_rn(1.9875691500e-4f, r, 1.3981999507e-3f);
  y1 = __fmaf_rn(4.1665795894e-2f, r, 1.6666665459e-1f);
  y2 = __fadd_rn(r, 1.0f);
  y  = __fmaf_rn(y, r, 8.3334519073e-3f);
  y1 = __fmaf_rn(y1, r, 5.0000001201e-1f);
  y  = __fmaf_rn(y, r3, y1);
  y  = __fmaf_rn(y, r2, y2);
  int mi = (int)m;
  return __fmul_rn(y, __int_as_float((mi + 127) << 23));
}

__global__ void k_init(){ if(threadIdx.x<8) g_max[threadIdx.x]=0u; }

// ---- merged abs-max over 4 tensors ------------------------------------------
__global__ void k_absmax_all(const float* __restrict__ hs,
                             const float* __restrict__ Wq,
                             const float* __restrict__ Wk,
                             const float* __restrict__ Wv){
  int slot = blockIdx.y;
  const float* x = (slot==0)? hs : (slot==1)? Wq : (slot==2)? Wk : Wv;
  int n4 = (slot==0)? (CM*CH/4) : (CH*CH/4);
  float m=0.f;
  for (int i=blockIdx.x*blockDim.x+threadIdx.x; i<n4; i+=gridDim.x*blockDim.x){
    float4 v=((const float4*)x)[i];
    m=fmaxf(m,fabsf(clipf(v.x))); m=fmaxf(m,fabsf(clipf(v.y)));
    m=fmaxf(m,fabsf(clipf(v.z))); m=fmaxf(m,fabsf(clipf(v.w)));
  }
  #pragma unroll
  for(int o=16;o;o>>=1) m=fmaxf(m,__shfl_xor_sync(0xffffffffu,m,o));
  if((threadIdx.x&31)==0) atomicMax(&g_max[slot],__float_as_uint(m));
}

// ---- merged dequant of 4 tensors (bit-exact sym_quant fwd value) ------------
__global__ void k_quant_all(const float* __restrict__ hs,
                            const float* __restrict__ Wq,
                            const float* __restrict__ Wk,
                            const float* __restrict__ Wv){
  int slot = blockIdx.y;
  const float* x = (slot==0)? hs : (slot==1)? Wq : (slot==2)? Wk : Wv;
  float* o = (slot==0)? g_xd : g_wd[slot-1];
  int n = (slot==0)? (CM*CH) : (CH*CH);
  float s = __fdiv_rn(127.f, slot_m(slot));
  for(int i=blockIdx.x*blockDim.x+threadIdx.x;i<n;i+=gridDim.x*blockDim.x){
    float q = rintf(__fmul_rn(clipf(x[i]), s));
    o[i] = __fdiv_rn(q, s);
  }
}

// ---- fp32 projection GEMM: one Eigen K=512 panel per block ------------------
// BM=BN=128, BK=16, 256 threads, 8x8 microtile (split fragments at +64),
// single smem buffer, register prefetch; forced 2 CTAs/SM (<=128 regs).
// Per output element: strictly ascending-k fp32 RN FMA chain from 0 within
// the panel (bit-identical). grid: (32, 8, 6), z = panel*3 + which.
__global__ __launch_bounds__(256,2) void k_gemm(){
  __shared__ float As[16][132];
  __shared__ float Bs[16][132];
  int which = blockIdx.z % 3, panel = blockIdx.z / 3;
  const float* A = g_xd;
  const float* W = g_wd[which];
  float* C = g_pan[panel][which];
  int bm=blockIdx.x, bn=blockIdx.y;
  int tid=threadIdx.x, ty=tid>>4, tx=tid&15;
  const float* Ab = A + (size_t)bm*128*CH + (size_t)panel*512;
  const float* Wb = W + (size_t)bn*128*CH + (size_t)panel*512;
  int lrow = tid>>1;           // 0..127
  int lk4  = (tid&1)*2;        // 0 or 2
  float4 pa0 = *(const float4*)(Ab + (size_t)lrow*CH + lk4*4);
  float4 pa1 = *(const float4*)(Ab + (size_t)lrow*CH + (lk4+1)*4);
  float4 pb0 = *(const float4*)(Wb + (size_t)lrow*CH + lk4*4);
  float4 pb1 = *(const float4*)(Wb + (size_t)lrow*CH + (lk4+1)*4);
  float acc[8][8]={};
  for(int kt=0;kt<32;kt++){
    __syncthreads();
    As[lk4*4+0][lrow]=pa0.x; As[lk4*4+1][lrow]=pa0.y;
    As[lk4*4+2][lrow]=pa0.z; As[lk4*4+3][lrow]=pa0.w;
    As[(lk4+1)*4+0][lrow]=pa1.x; As[(lk4+1)*4+1][lrow]=pa1.y;
    As[(lk4+1)*4+2][lrow]=pa1.z; As[(lk4+1)*4+3][lrow]=pa1.w;
    Bs[lk4*4+0][lrow]=pb0.x; Bs[lk4*4+1][lrow]=pb0.y;
    Bs[lk4*4+2][lrow]=pb0.z; Bs[lk4*4+3][lrow]=pb0.w;
    Bs[(lk4+1)*4+0][lrow]=pb1.x; Bs[(lk4+1)*4+1][lrow]=pb1.y;
    Bs[(lk4+1)*4+2][lrow]=pb1.z; Bs[(lk4+1)*4+3][lrow]=pb1.w;
    __syncthreads();
    if(kt<31){
      pa0 = *(const float4*)(Ab + (size_t)lrow*CH + (kt+1)*16 + lk4*4);
      pa1 = *(const float4*)(Ab + (size_t)lrow*CH + (kt+1)*16 + (lk4+1)*4);
      pb0 = *(const float4*)(Wb + (size_t)lrow*CH + (kt+1)*16 + lk4*4);
      pb1 = *(const float4*)(Wb + (size_t)lrow*CH + (kt+1)*16 + (lk4+1)*4);
    }
    #pragma unroll
    for(int kk=0;kk<16;kk++){
      float a[8], b[8];
      *(float4*)&a[0] = *(const float4*)&As[kk][ty*4];
      *(float4*)&a[4] = *(const float4*)&As[kk][64+ty*4];
      *(float4*)&b[0] = *(const float4*)&Bs[kk][tx*4];
      *(float4*)&b[4] = *(const float4*)&Bs[kk][64+tx*4];
      #pragma unroll
      for(int i=0;i<8;i++)
        #pragma unroll
        for(int j=0;j<8;j++) acc[i][j]=__fmaf_rn(a[i],b[j],acc[i][j]);
    }
  }
  #pragma unroll
  for(int i=0;i<8;i++){
    int m = bm*128 + ((i<4)? (ty*4+i) : (64+ty*4+i-4));
    float4 c0 = make_float4(acc[i][0],acc[i][1],acc[i][2],acc[i][3]);
    float4 c1 = make_float4(acc[i][4],acc[i][5],acc[i][6],acc[i][7]);
    *(float4*)&C[(size_t)m*CH + bn*128 + tx*4]      = c0;
    *(float4*)&C[(size_t)m*CH + bn*128 + 64 + tx*4] = c1;
  }
}

// ---- combine panels + bias + abs-max (bit-exact old epilogue) ---------------
__global__ void k_bias_max(const float* __restrict__ bq,
                           const float* __restrict__ bk,
                           const float* __restrict__ bv){
  int which = blockIdx.y;
  const float* bias = (which==0)? bq : (which==1)? bk : bv;
  const float* P1 = g_pan[0][which];
  const float* P2 = g_pan[1][which];
  float* C = g_lin[which];
  const int n = CM*CH;
  float lm=0.f;
  for(int i=blockIdx.x*blockDim.x+threadIdx.x;i<n;i+=gridDim.x*blockDim.x){
    float c = __fadd_rn(__fadd_rn(P1[i], P2[i]), bias[i&(CH-1)]);
    C[i]=c;
    lm=fmaxf(lm,fabsf(clipf(c)));
  }
  #pragma unroll
  for(int o=16;o;o>>=1) lm=fmaxf(lm,__shfl_xor_sync(0xffffffffu,lm,o));
  if((threadIdx.x&31)==0) atomicMax(&g_max[4+which],__float_as_uint(lm));
}

// ---- merged q/k/v re-quantization: grid.y = which (0:q,1:k,2:v) -------------
__global__ void k_quant_heads_all(float* __restrict__ vq_out){
  int which = blockIdx.y;
  const float* src = g_lin[which];
  float s = __fdiv_rn(127.f, slot_m(4+which));
  const int n = CB*CNH*CS*CDH;
  if(which<2){
    float* dst = (which==0)? g_qf : g_kf;
    for(int i=blockIdx.x*blockDim.x+threadIdx.x;i<n;i+=gridDim.x*blockDim.x){
      int d=i&63, s_=(i>>6)&1023, h=(i>>16)&15, b=i>>20;
      float v=src[((size_t)(b*CS+s_))*CH + h*CDH + d];
      float q=rintf(__fmul_rn(clipf(v),s));
      dst[i]=__fdiv_rn(q, s);
    }
  } else {
    for(int i=blockIdx.x*blockDim.x+threadIdx.x;i<n;i+=gridDim.x*blockDim.x){
      int d=i&63, s_=(i>>6)&1023, h=(i>>16)&15, b=i>>20;
      float v=src[((size_t)(b*CS+s_))*CH + h*CDH + d];
      float vc=clipf(v);
      float q=rintf(__fmul_rn(vc,s));
      if(vq_out) vq_out[i]=__fdiv_rn(q, s);
      g_v8t[(((size_t)(b*CNH+h))*CDH+d)*CS + s_]=(int8_t)(int)q;
    }
  }
}

// ---- scores: bit-exact ascending-d fp32 FMA chain, split-fragment 8x8 -------
__global__ __launch_bounds__(256,2) void k_scores(const float* __restrict__ mask,
                                                  float* __restrict__ ss){
  extern __shared__ float sm[];
  float* qs = sm;             // [64 d][132]
  float* ks = sm + 64*132;    // [64 d][132]
  int rt=blockIdx.x, ct=blockIdx.y, bh=blockIdx.z;
  int b = bh>>4;
  int tid=threadIdx.x, ty=tid>>4, tx=tid&15;
  const float* qg = g_qf + ((size_t)bh*CS + (size_t)rt*128)*CDH;
  const float* kg = g_kf + ((size_t)bh*CS + (size_t)ct*128)*CDH;
  for(int idx=tid; idx<128*16; idx+=256){
    int d4=idx&15, row=idx>>4;
    float4 v = *(const float4*)(qg + (size_t)row*CDH + d4*4);
    qs[(d4*4+0)*132+row]=v.x; qs[(d4*4+1)*132+row]=v.y;
    qs[(d4*4+2)*132+row]=v.z; qs[(d4*4+3)*132+row]=v.w;
    float4 u = *(const float4*)(kg + (size_t)row*CDH + d4*4);
    ks[(d4*4+0)*132+row]=u.x; ks[(d4*4+1)*132+row]=u.y;
    ks[(d4*4+2)*132+row]=u.z; ks[(d4*4+3)*132+row]=u.w;
  }
  __syncthreads();
  float acc[8][8]={};
  for(int d=0; d<64; d++){               // ascending-d chain per element
    float a[8], bv[8];
    *(float4*)&a[0]  = *(const float4*)&qs[d*132 + ty*4];
    *(float4*)&a[4]  = *(const float4*)&qs[d*132 + 64 + ty*4];
    *(float4*)&bv[0] = *(const float4*)&ks[d*132 + tx*4];
    *(float4*)&bv[4] = *(const float4*)&ks[d*132 + 64 + tx*4];
    #pragma unroll
    for(int i=0;i<8;i++)
      #pragma unroll
      for(int j=0;j<8;j++) acc[i][j]=__fmaf_rn(a[i],bv[j],acc[i][j]);
  }
  #pragma unroll
  for(int i=0;i<8;i++){
    int row = rt*128 + ((i<4)? (ty*4+i) : (64+ty*4+i-4));
    #pragma unroll
    for(int jh=0;jh<2;jh++){
      int col0 = ct*128 + ((jh==0)? (tx*4) : (64+tx*4));
      float4 sv;
      sv.x = __fadd_rn(__fmul_rn(acc[i][jh*4+0], 0.125f), mask[b*CS+col0+0]);
      sv.y = __fadd_rn(__fmul_rn(acc[i][jh*4+1], 0.125f), mask[b*CS+col0+1]);
      sv.z = __fadd_rn(__fmul_rn(acc[i][jh*4+2], 0.125f), mask[b*CS+col0+2]);
      sv.w = __fadd_rn(__fmul_rn(acc[i][jh*4+3], 0.125f), mask[b*CS+col0+3]);
      *(float4*)&ss[((size_t)bh*CS + row)*CS + col0] = sv;
    }
  }
}

// ---- softmax per row (unchanged bits) ----------------------------------------
__global__ __launch_bounds__(256) void k_softmax(const float* __restrict__ ssrc,
                                                 float* __restrict__ pdst,
                                                 int nrows){
  __shared__ float red[64];
  int rowid = nrows - 1 - blockIdx.x;
  size_t base = (size_t)rowid * CS;
  int tid=threadIdx.x, lane=tid&31, warp=tid>>5;
  float4 x = *(const float4*)(ssrc + base + tid*4);
  float m = fmaxf(fmaxf(x.x,x.y), fmaxf(x.z,x.w));
  #pragma unroll
  for(int o=16;o;o>>=1) m=fmaxf(m,__shfl_xor_sync(0xffffffffu,m,o));
  if(lane==0) red[warp]=m;
  __syncthreads();
  if(tid<8){ float t=red[tid];
    #pragma unroll
    for(int o=4;o;o>>=1) t=fmaxf(t,__shfl_xor_sync(0xffu,t,o));
    red[32+tid]=t; }
  __syncthreads();
  float rowmax = red[32];
  float e0=exp_eig(__fsub_rn(x.x,rowmax));
  float e1=exp_eig(__fsub_rn(x.y,rowmax));
  float e2=exp_eig(__fsub_rn(x.z,rowmax));
  float e3=exp_eig(__fsub_rn(x.w,rowmax));
  float v = ((e0+e1)+(e2+e3));
  __shared__ float tree[256];
  tree[tid]=v; __syncthreads();
  if(tid<128) tree[tid]=tree[tid]+tree[tid+128];
  __syncthreads();
  if(tid<64) tree[tid]=tree[tid]+tree[tid+64];
  __syncthreads();
  if(tid<32){
    float t=tree[tid]+tree[tid+32];
    #pragma unroll
    for(int o=16;o;o>>=1) t = t + __shfl_down_sync(0xffffffffu,t,o);
    if(tid==0) red[33]=t;
  }
  __syncthreads();
  float sum = red[33];
  float4 p;
  p.x=__fdiv_rn(e0,sum); p.y=__fdiv_rn(e1,sum);
  p.z=__fdiv_rn(e2,sum); p.w=__fdiv_rn(e3,sum);
  *(float4*)(pdst + base + tid*4) = p;
  if(tid==0) atomicMax(&g_max[7],__float_as_uint(__fdiv_rn(1.f,sum)));
}

// ---- PV (unchanged): context_ = probs_q @ v_q -------------------------------
__global__ __launch_bounds__(256) void k_pv(const float* __restrict__ probs_in,
     float* __restrict__ ctxp, float* __restrict__ ctx){
  __shared__ int ps[128][33];
  __shared__ int vs[64][33];
  int mt=blockIdx.x, bh=blockIdx.y;
  int b=bh>>4, h=bh&15;
  const float* pg = probs_in + (((size_t)bh)*CS + (size_t)mt*128)*CS;
  const int* vtg = (const int*)(g_v8t + (size_t)bh*CDH*CS);
  float sp = __fdiv_rn(127.f, slot_m(7));
  int tid=threadIdx.x, ty=tid>>4, tx=tid&15;
  int acc[8][4]={};
  for(int kc=0;kc<8;kc++){
    for(int idx=tid; idx<128*32; idx+=256){
      int r=idx>>5, w=idx&31;
      float4 p4=*(const float4*)(pg + (size_t)r*CS + kc*128 + w*4);
      int b0=((int)rintf(__fmul_rn(p4.x,sp)))&0xFF;
      int b1=((int)rintf(__fmul_rn(p4.y,sp)))&0xFF;
      int b2=((int)rintf(__fmul_rn(p4.z,sp)))&0xFF;
      int b3=((int)rintf(__fmul_rn(p4.w,sp)))&0xFF;
      ps[r][w]= b0|(b1<<8)|(b2<<16)|(b3<<24);
    }
    for(int idx=tid; idx<64*32; idx+=256){
      int d=idx>>5, w=idx&31;
      vs[d][w]=vtg[(size_t)d*(CS/4)+kc*32+w];
    }
    __syncthreads();
    #pragma unroll
    for(int w=0;w<32;w++){
      int a[8],bb[4];
      #pragma unroll
      for(int i=0;i<8;i++) a[i]=ps[ty*8+i][w];
      #pragma unroll
      for(int j=0;j<4;j++) bb[j]=vs[tx*4+j][w];
      #pragma unroll
      for(int i=0;i<8;i++)
        #pragma unroll
        for(int j=0;j<4;j++) acc[i][j]=__dp4a(a[i],bb[j],acc[i][j]);
    }
    __syncthreads();
  }
  double inv = 1.0/((double)__fdiv_rn(127.f,slot_m(7))*(double)__fdiv_rn(127.f,slot_m(6)));
  #pragma unroll
  for(int i=0;i<8;i++){
    int srow=mt*128+ty*8+i;
    #pragma unroll
    for(int j=0;j<4;j++){
      int d=tx*4+j;
      float c=(float)((double)acc[i][j]*inv);
      if(ctxp) ctxp[(((size_t)bh)*CS+srow)*CDH+d]=c;
      ctx[((size_t)(b*CS+srow))*CH + h*CDH + d]=c;
    }
  }
}

// ---------------- launch ----------------
extern "C" void kernel_launch(void* const* d_in, const int* in_sizes, int n_in,
                              void* d_out, int out_size){
  const float* hs  =(const float*)d_in[0];
  const float* mask=(const float*)d_in[1];
  const float* Wq  =(const float*)d_in[2];
  const float* bq  =(const float*)d_in[3];
  const float* Wk  =(const float*)d_in[4];
  const float* bk  =(const float*)d_in[5];
  const float* Wv  =(const float*)d_in[6];
  const float* bv  =(const float*)d_in[7];
  float* out=(float*)d_out;

  const size_t n_ctx=(size_t)CB*CS*CH;
  const size_t n_sc =(size_t)CB*CNH*CS*CS;
  float *ctx=out, *scores=nullptr, *probs=nullptr, *ctxp=nullptr, *vq=nullptr;
  if((size_t)out_size >= 3*n_ctx + 2*n_sc){
    scores=out+n_ctx; probs=scores+n_sc; ctxp=probs+n_sc; vq=ctxp+n_ctx;
  }
  float* sc_buf = scores;
  float* pr_buf = probs;
  if(!sc_buf){ void* p; cudaGetSymbolAddress(&p, g_sc_fb); sc_buf=(float*)p; }
  if(!pr_buf){ void* p; cudaGetSymbolAddress(&p, g_pr_fb); pr_buf=(float*)p; }

  k_init<<<1,32>>>();
  k_absmax_all<<<dim3(256,4),256>>>(hs,Wq,Wk,Wv);
  k_quant_all<<<dim3(1024,4),256>>>(hs,Wq,Wk,Wv);

  k_gemm<<<dim3(CM/128, CH/128, 6),256>>>();
  k_bias_max<<<dim3(2048,3),256>>>(bq,bk,bv);

  k_quant_heads_all<<<dim3(1024,3),256>>>(vq);

  const int sc_smem = 64*132*2*sizeof(float);   // 67,584 B
  cudaFuncSetAttribute(k_scores, cudaFuncAttributeMaxDynamicSharedMemorySize, sc_smem);
  k_scores<<<dim3(CS/128,CS/128,CB*CNH),256,sc_smem>>>(mask, sc_buf);

  k_softmax<<<CB*CNH*CS,256>>>(sc_buf, pr_buf, CB*CNH*CS);

  k_pv<<<dim3(CS/128,CB*CNH),256>>>(pr_buf, ctxp, ctx);
}

// round 17
// speedup vs baseline: 1.3307x; 1.0080x over previous
#include <cuda_runtime.h>
#include <cstdint>
#include <math.h>

#define CB 4
#define CS 1024
#define CH 1024
#define CNH 16
#define CDH 64
#define CM (CB*CS)
#define CLIPV 2.5f

// Correctly-rounded a/b given b and y=__frcp_rn(b) (Markstein; bit-identical
// to __fdiv_rn(a,b) for normal operands, which all uses here are).
__device__ __forceinline__ float div_rn_fast(float a, float b, float y){
  float q0 = __fmul_rn(a, y);
  float r  = __fmaf_rn(-b, q0, a);
  return __fmaf_rn(r, y, q0);
}

// ---------------- scratch (device globals; no allocations allowed) ----------
__device__ unsigned g_max[8];   // 0 hidden,1 Wq,2 Wk,3 Wv,4 q,5 k,6 v,7 probs
__device__ float  g_xd[(size_t)CM*CH];                // dequant hidden (bit-exact)
__device__ float  g_wd[3][(size_t)CH*CH];             // dequant weights (bit-exact)
__device__ float  g_pan[2][3][(size_t)CM*CH];         // per-panel GEMM partials
__device__ float  g_lin[3][(size_t)CM*CH];            // q,k,v fp32 [B,S,H]
__device__ float  g_qf[(size_t)CB*CNH*CS*CDH];        // dequant q [b,h,s,d] fp32
__device__ float  g_kf[(size_t)CB*CNH*CS*CDH];        // dequant k [b,h,s,d] fp32
__device__ int8_t g_v8t[(size_t)CB*CNH*CDH*CS];       // v codes [b,h,d,s]
__device__ float  g_sc_fb[(size_t)CB*CNH*CS*CS];      // fallback scores
__device__ float  g_pr_fb[(size_t)CB*CNH*CS*CS];      // fallback probs

__device__ __forceinline__ float clipf(float v){ return fminf(fmaxf(v,-CLIPV),CLIPV); }
__device__ __forceinline__ float slot_m(int s){ return fmaxf(__uint_as_float(g_max[s]),1e-8f); }

// Eigen pexp<float> replica (unchanged bits).
__device__ __forceinline__ float exp_eig(float x){
  float m = floorf(__fmaf_rn(x, 1.44269504088896341f, 0.5f));
  float r = __fmaf_rn(m, -0.693359375f, x);
  r = __fmaf_rn(m, 2.12194440e-4f, r);
  float r2 = __fmul_rn(r, r);
  float r3 = __fmul_rn(r2, r);
  float y, y1, y2;
  y  = __fmaf_rn(1.9875691500e-4f, r, 1.3981999507e-3f);
  y1 = __fmaf_rn(4.1665795894e-2f, r, 1.6666665459e-1f);
  y2 = __fadd_rn(r, 1.0f);
  y  = __fmaf_rn(y, r, 8.3334519073e-3f);
  y1 = __fmaf_rn(y1, r, 5.0000001201e-1f);
  y  = __fmaf_rn(y, r3, y1);
  y  = __fmaf_rn(y, r2, y2);
  int mi = (int)m;
  return __fmul_rn(y, __int_as_float((mi + 127) << 23));
}

__global__ void k_init(){ if(threadIdx.x<8) g_max[threadIdx.x]=0u; }

// ---- merged abs-max over 4 tensors ------------------------------------------
__global__ void k_absmax_all(const float* __restrict__ hs,
                             const float* __restrict__ Wq,
                             const float* __restrict__ Wk,
                             const float* __restrict__ Wv){
  int slot = blockIdx.y;
  const float* x = (slot==0)? hs : (slot==1)? Wq : (slot==2)? Wk : Wv;
  int n4 = (slot==0)? (CM*CH/4) : (CH*CH/4);
  float m=0.f;
  for (int i=blockIdx.x*blockDim.x+threadIdx.x; i<n4; i+=gridDim.x*blockDim.x){
    float4 v=((const float4*)x)[i];
    m=fmaxf(m,fabsf(clipf(v.x))); m=fmaxf(m,fabsf(clipf(v.y)));
    m=fmaxf(m,fabsf(clipf(v.z))); m=fmaxf(m,fabsf(clipf(v.w)));
  }
  #pragma unroll
  for(int o=16;o;o>>=1) m=fmaxf(m,__shfl_xor_sync(0xffffffffu,m,o));
  if((threadIdx.x&31)==0) atomicMax(&g_max[slot],__float_as_uint(m));
}

// ---- merged dequant of 4 tensors (bit-exact sym_quant fwd value) ------------
__global__ void k_quant_all(const float* __restrict__ hs,
                            const float* __restrict__ Wq,
                            const float* __restrict__ Wk,
                            const float* __restrict__ Wv){
  int slot = blockIdx.y;
  const float* x = (slot==0)? hs : (slot==1)? Wq : (slot==2)? Wk : Wv;
  float* o = (slot==0)? g_xd : g_wd[slot-1];
  int n = (slot==0)? (CM*CH) : (CH*CH);
  float s = __fdiv_rn(127.f, slot_m(slot));
  float ys = __frcp_rn(s);
  for(int i=blockIdx.x*blockDim.x+threadIdx.x;i<n;i+=gridDim.x*blockDim.x){
    float q = rintf(__fmul_rn(clipf(x[i]), s));
    o[i] = div_rn_fast(q, s, ys);          // == __fdiv_rn(q, s)
  }
}

// ---- fp32 projection GEMM: one Eigen K=512 panel per block ------------------
// BM=BN=128, BK=16, 256 threads, 8x8 microtile (split fragments at +64),
// single smem buffer, register prefetch; forced 2 CTAs/SM (<=128 regs).
__global__ __launch_bounds__(256,2) void k_gemm(){
  __shared__ float As[16][132];
  __shared__ float Bs[16][132];
  int which = blockIdx.z % 3, panel = blockIdx.z / 3;
  const float* A = g_xd;
  const float* W = g_wd[which];
  float* C = g_pan[panel][which];
  int bm=blockIdx.x, bn=blockIdx.y;
  int tid=threadIdx.x, ty=tid>>4, tx=tid&15;
  const float* Ab = A + (size_t)bm*128*CH + (size_t)panel*512;
  const float* Wb = W + (size_t)bn*128*CH + (size_t)panel*512;
  int lrow = tid>>1;           // 0..127
  int lk4  = (tid&1)*2;        // 0 or 2
  float4 pa0 = *(const float4*)(Ab + (size_t)lrow*CH + lk4*4);
  float4 pa1 = *(const float4*)(Ab + (size_t)lrow*CH + (lk4+1)*4);
  float4 pb0 = *(const float4*)(Wb + (size_t)lrow*CH + lk4*4);
  float4 pb1 = *(const float4*)(Wb + (size_t)lrow*CH + (lk4+1)*4);
  float acc[8][8]={};
  for(int kt=0;kt<32;kt++){
    __syncthreads();
    As[lk4*4+0][lrow]=pa0.x; As[lk4*4+1][lrow]=pa0.y;
    As[lk4*4+2][lrow]=pa0.z; As[lk4*4+3][lrow]=pa0.w;
    As[(lk4+1)*4+0][lrow]=pa1.x; As[(lk4+1)*4+1][lrow]=pa1.y;
    As[(lk4+1)*4+2][lrow]=pa1.z; As[(lk4+1)*4+3][lrow]=pa1.w;
    Bs[lk4*4+0][lrow]=pb0.x; Bs[lk4*4+1][lrow]=pb0.y;
    Bs[lk4*4+2][lrow]=pb0.z; Bs[lk4*4+3][lrow]=pb0.w;
    Bs[(lk4+1)*4+0][lrow]=pb1.x; Bs[(lk4+1)*4+1][lrow]=pb1.y;
    Bs[(lk4+1)*4+2][lrow]=pb1.z; Bs[(lk4+1)*4+3][lrow]=pb1.w;
    __syncthreads();
    if(kt<31){
      pa0 = *(const float4*)(Ab + (size_t)lrow*CH + (kt+1)*16 + lk4*4);
      pa1 = *(const float4*)(Ab + (size_t)lrow*CH + (kt+1)*16 + (lk4+1)*4);
      pb0 = *(const float4*)(Wb + (size_t)lrow*CH + (kt+1)*16 + lk4*4);
      pb1 = *(const float4*)(Wb + (size_t)lrow*CH + (kt+1)*16 + (lk4+1)*4);
    }
    #pragma unroll
    for(int kk=0;kk<16;kk++){
      float a[8], b[8];
      *(float4*)&a[0] = *(const float4*)&As[kk][ty*4];
      *(float4*)&a[4] = *(const float4*)&As[kk][64+ty*4];
      *(float4*)&b[0] = *(const float4*)&Bs[kk][tx*4];
      *(float4*)&b[4] = *(const float4*)&Bs[kk][64+tx*4];
      #pragma unroll
      for(int i=0;i<8;i++)
        #pragma unroll
        for(int j=0;j<8;j++) acc[i][j]=__fmaf_rn(a[i],b[j],acc[i][j]);
    }
  }
  #pragma unroll
  for(int i=0;i<8;i++){
    int m = bm*128 + ((i<4)? (ty*4+i) : (64+ty*4+i-4));
    float4 c0 = make_float4(acc[i][0],acc[i][1],acc[i][2],acc[i][3]);
    float4 c1 = make_float4(acc[i][4],acc[i][5],acc[i][6],acc[i][7]);
    *(float4*)&C[(size_t)m*CH + bn*128 + tx*4]      = c0;
    *(float4*)&C[(size_t)m*CH + bn*128 + 64 + tx*4] = c1;
  }
}

// ---- combine panels + bias + abs-max (bit-exact old epilogue) ---------------
__global__ void k_bias_max(const float* __restrict__ bq,
                           const float* __restrict__ bk,
                           const float* __restrict__ bv){
  int which = blockIdx.y;
  const float* bias = (which==0)? bq : (which==1)? bk : bv;
  const float* P1 = g_pan[0][which];
  const float* P2 = g_pan[1][which];
  float* C = g_lin[which];
  const int n = CM*CH;
  float lm=0.f;
  for(int i=blockIdx.x*blockDim.x+threadIdx.x;i<n;i+=gridDim.x*blockDim.x){
    float c = __fadd_rn(__fadd_rn(P1[i], P2[i]), bias[i&(CH-1)]);
    C[i]=c;
    lm=fmaxf(lm,fabsf(clipf(c)));
  }
  #pragma unroll
  for(int o=16;o;o>>=1) lm=fmaxf(lm,__shfl_xor_sync(0xffffffffu,lm,o));
  if((threadIdx.x&31)==0) atomicMax(&g_max[4+which],__float_as_uint(lm));
}

// ---- merged q/k/v re-quantization: grid.y = which (0:q,1:k,2:v) -------------
__global__ void k_quant_heads_all(float* __restrict__ vq_out){
  int which = blockIdx.y;
  const float* src = g_lin[which];
  float s = __fdiv_rn(127.f, slot_m(4+which));
  float ys = __frcp_rn(s);
  const int n = CB*CNH*CS*CDH;
  if(which<2){
    float* dst = (which==0)? g_qf : g_kf;
    for(int i=blockIdx.x*blockDim.x+threadIdx.x;i<n;i+=gridDim.x*blockDim.x){
      int d=i&63, s_=(i>>6)&1023, h=(i>>16)&15, b=i>>20;
      float v=src[((size_t)(b*CS+s_))*CH + h*CDH + d];
      float q=rintf(__fmul_rn(clipf(v),s));
      dst[i]=div_rn_fast(q, s, ys);        // == __fdiv_rn(q, s)
    }
  } else {
    for(int i=blockIdx.x*blockDim.x+threadIdx.x;i<n;i+=gridDim.x*blockDim.x){
      int d=i&63, s_=(i>>6)&1023, h=(i>>16)&15, b=i>>20;
      float v=src[((size_t)(b*CS+s_))*CH + h*CDH + d];
      float vc=clipf(v);
      float q=rintf(__fmul_rn(vc,s));
      if(vq_out) vq_out[i]=div_rn_fast(q, s, ys);
      g_v8t[(((size_t)(b*CNH+h))*CDH+d)*CS + s_]=(int8_t)(int)q;
    }
  }
}

// ---- scores: bit-exact ascending-d fp32 FMA chain, split-fragment 8x8 -------
__global__ __launch_bounds__(256,2) void k_scores(const float* __restrict__ mask,
                                                  float* __restrict__ ss){
  extern __shared__ float sm[];
  float* qs = sm;             // [64 d][132]
  float* ks = sm + 64*132;    // [64 d][132]
  int rt=blockIdx.x, ct=blockIdx.y, bh=blockIdx.z;
  int b = bh>>4;
  int tid=threadIdx.x, ty=tid>>4, tx=tid&15;
  const float* qg = g_qf + ((size_t)bh*CS + (size_t)rt*128)*CDH;
  const float* kg = g_kf + ((size_t)bh*CS + (size_t)ct*128)*CDH;
  for(int idx=tid; idx<128*16; idx+=256){
    int d4=idx&15, row=idx>>4;
    float4 v = *(const float4*)(qg + (size_t)row*CDH + d4*4);
    qs[(d4*4+0)*132+row]=v.x; qs[(d4*4+1)*132+row]=v.y;
    qs[(d4*4+2)*132+row]=v.z; qs[(d4*4+3)*132+row]=v.w;
    float4 u = *(const float4*)(kg + (size_t)row*CDH + d4*4);
    ks[(d4*4+0)*132+row]=u.x; ks[(d4*4+1)*132+row]=u.y;
    ks[(d4*4+2)*132+row]=u.z; ks[(d4*4+3)*132+row]=u.w;
  }
  __syncthreads();
  float acc[8][8]={};
  for(int d=0; d<64; d++){               // ascending-d chain per element
    float a[8], bv[8];
    *(float4*)&a[0]  = *(const float4*)&qs[d*132 + ty*4];
    *(float4*)&a[4]  = *(const float4*)&qs[d*132 + 64 + ty*4];
    *(float4*)&bv[0] = *(const float4*)&ks[d*132 + tx*4];
    *(float4*)&bv[4] = *(const float4*)&ks[d*132 + 64 + tx*4];
    #pragma unroll
    for(int i=0;i<8;i++)
      #pragma unroll
      for(int j=0;j<8;j++) acc[i][j]=__fmaf_rn(a[i],bv[j],acc[i][j]);
  }
  #pragma unroll
  for(int i=0;i<8;i++){
    int row = rt*128 + ((i<4)? (ty*4+i) : (64+ty*4+i-4));
    #pragma unroll
    for(int jh=0;jh<2;jh++){
      int col0 = ct*128 + ((jh==0)? (tx*4) : (64+tx*4));
      float4 sv;
      sv.x = __fadd_rn(__fmul_rn(acc[i][jh*4+0], 0.125f), mask[b*CS+col0+0]);
      sv.y = __fadd_rn(__fmul_rn(acc[i][jh*4+1], 0.125f), mask[b*CS+col0+1]);
      sv.z = __fadd_rn(__fmul_rn(acc[i][jh*4+2], 0.125f), mask[b*CS+col0+2]);
      sv.w = __fadd_rn(__fmul_rn(acc[i][jh*4+3], 0.125f), mask[b*CS+col0+3]);
      *(float4*)&ss[((size_t)bh*CS + row)*CS + col0] = sv;
    }
  }
}

// ---- softmax per row: Markstein divides (bit-identical to __fdiv_rn) --------
__global__ __launch_bounds__(256) void k_softmax(const float* __restrict__ ssrc,
                                                 float* __restrict__ pdst,
                                                 int nrows){
  __shared__ float red[64];
  int rowid = nrows - 1 - blockIdx.x;
  size_t base = (size_t)rowid * CS;
  int tid=threadIdx.x, lane=tid&31, warp=tid>>5;
  float4 x = *(const float4*)(ssrc + base + tid*4);
  float m = fmaxf(fmaxf(x.x,x.y), fmaxf(x.z,x.w));
  #pragma unroll
  for(int o=16;o;o>>=1) m=fmaxf(m,__shfl_xor_sync(0xffffffffu,m,o));
  if(lane==0) red[warp]=m;
  __syncthreads();
  if(tid<8){ float t=red[tid];
    #pragma unroll
    for(int o=4;o;o>>=1) t=fmaxf(t,__shfl_xor_sync(0xffu,t,o));
    red[32+tid]=t; }
  __syncthreads();
  float rowmax = red[32];
  float e0=exp_eig(__fsub_rn(x.x,rowmax));
  float e1=exp_eig(__fsub_rn(x.y,rowmax));
  float e2=exp_eig(__fsub_rn(x.z,rowmax));
  float e3=exp_eig(__fsub_rn(x.w,rowmax));
  float v = ((e0+e1)+(e2+e3));
  __shared__ float tree[256];
  tree[tid]=v; __syncthreads();
  if(tid<128) tree[tid]=tree[tid]+tree[tid+128];
  __syncthreads();
  if(tid<64) tree[tid]=tree[tid]+tree[tid+64];
  __syncthreads();
  if(tid<32){
    float t=tree[tid]+tree[tid+32];
    #pragma unroll
    for(int o=16;o;o>>=1) t = t + __shfl_down_sync(0xffffffffu,t,o);
    if(tid==0) red[33]=t;
  }
  __syncthreads();
  float sum = red[33];
  float yr = __frcp_rn(sum);               // correctly-rounded 1/sum
  float4 p;
  p.x = div_rn_fast(e0, sum, yr);
  p.y = div_rn_fast(e1, sum, yr);
  p.z = div_rn_fast(e2, sum, yr);
  p.w = div_rn_fast(e3, sum, yr);
  *(float4*)(pdst + base + tid*4) = p;
  if(tid==0) atomicMax(&g_max[7],__float_as_uint(yr));  // == __fdiv_rn(1,sum)
}

// ---- PV: context_ = probs_q @ v_q (PRMT pack; exact dp4a + double dequant) --
__global__ __launch_bounds__(256) void k_pv(const float* __restrict__ probs_in,
     float* __restrict__ ctxp, float* __restrict__ ctx){
  __shared__ int ps[128][33];
  __shared__ int vs[64][33];
  int mt=blockIdx.x, bh=blockIdx.y;
  int b=bh>>4, h=bh&15;
  const float* pg = probs_in + (((size_t)bh)*CS + (size_t)mt*128)*CS;
  const int* vtg = (const int*)(g_v8t + (size_t)bh*CDH*CS);
  float sp = __fdiv_rn(127.f, slot_m(7));
  int tid=threadIdx.x, ty=tid>>4, tx=tid&15;
  int acc[8][4]={};
  for(int kc=0;kc<8;kc++){
    for(int idx=tid; idx<128*32; idx+=256){
      int r=idx>>5, w=idx&31;
      float4 p4=*(const float4*)(pg + (size_t)r*CS + kc*128 + w*4);
      int c0=__float2int_rn(__fmul_rn(p4.x,sp));
      int c1=__float2int_rn(__fmul_rn(p4.y,sp));
      int c2=__float2int_rn(__fmul_rn(p4.z,sp));
      int c3=__float2int_rn(__fmul_rn(p4.w,sp));
      ps[r][w]=__byte_perm(__byte_perm(c0,c1,0x0040),
                           __byte_perm(c2,c3,0x0040), 0x5410);
    }
    for(int idx=tid; idx<64*32; idx+=256){
      int d=idx>>5, w=idx&31;
      vs[d][w]=vtg[(size_t)d*(CS/4)+kc*32+w];
    }
    __syncthreads();
    #pragma unroll
    for(int w=0;w<32;w++){
      int a[8],bb[4];
      #pragma unroll
      for(int i=0;i<8;i++) a[i]=ps[ty*8+i][w];
      #pragma unroll
      for(int j=0;j<4;j++) bb[j]=vs[tx*4+j][w];
      #pragma unroll
      for(int i=0;i<8;i++)
        #pragma unroll
        for(int j=0;j<4;j++) acc[i][j]=__dp4a(a[i],bb[j],acc[i][j]);
    }
    __syncthreads();
  }
  double inv = 1.0/((double)__fdiv_rn(127.f,slot_m(7))*(double)__fdiv_rn(127.f,slot_m(6)));
  #pragma unroll
  for(int i=0;i<8;i++){
    int srow=mt*128+ty*8+i;
    #pragma unroll
    for(int j=0;j<4;j++){
      int d=tx*4+j;
      float c=(float)((double)acc[i][j]*inv);
      if(ctxp) ctxp[(((size_t)bh)*CS+srow)*CDH+d]=c;
      ctx[((size_t)(b*CS+srow))*CH + h*CDH + d]=c;
    }
  }
}

// ---------------- launch ----------------
extern "C" void kernel_launch(void* const* d_in, const int* in_sizes, int n_in,
                              void* d_out, int out_size){
  const float* hs  =(const float*)d_in[0];
  const float* mask=(const float*)d_in[1];
  const float* Wq  =(const float*)d_in[2];
  const float* bq  =(const float*)d_in[3];
  const float* Wk  =(const float*)d_in[4];
  const float* bk  =(const float*)d_in[5];
  const float* Wv  =(const float*)d_in[6];
  const float* bv  =(const float*)d_in[7];
  float* out=(float*)d_out;

  const size_t n_ctx=(size_t)CB*CS*CH;
  const size_t n_sc =(size_t)CB*CNH*CS*CS;
  float *ctx=out, *scores=nullptr, *probs=nullptr, *ctxp=nullptr, *vq=nullptr;
  if((size_t)out_size >= 3*n_ctx + 2*n_sc){
    scores=out+n_ctx; probs=scores+n_sc; ctxp=probs+n_sc; vq=ctxp+n_ctx;
  }
  float* sc_buf = scores;
  float* pr_buf = probs;
  if(!sc_buf){ void* p; cudaGetSymbolAddress(&p, g_sc_fb); sc_buf=(float*)p; }
  if(!pr_buf){ void* p; cudaGetSymbolAddress(&p, g_pr_fb); pr_buf=(float*)p; }

  k_init<<<1,32>>>();
  k_absmax_all<<<dim3(256,4),256>>>(hs,Wq,Wk,Wv);
  k_quant_all<<<dim3(1024,4),256>>>(hs,Wq,Wk,Wv);

  k_gemm<<<dim3(CM/128, CH/128, 6),256>>>();
  k_bias_max<<<dim3(2048,3),256>>>(bq,bk,bv);

  k_quant_heads_all<<<dim3(1024,3),256>>>(vq);

  const int sc_smem = 64*132*2*sizeof(float);   // 67,584 B
  cudaFuncSetAttribute(k_scores, cudaFuncAttributeMaxDynamicSharedMemorySize, sc_smem);
  k_scores<<<dim3(CS/128,CS/128,CB*CNH),256,sc_smem>>>(mask, sc_buf);

  k_softmax<<<CB*CNH*CS,256>>>(sc_buf, pr_buf, CB*CNH*CS);

  k_pv<<<dim3(CS/128,CB*CNH),256>>>(pr_buf, ctxp, ctx);
}